// round 9
// baseline (speedup 1.0000x reference)
#include <cuda_runtime.h>
#include <cuda_fp16.h>
#include <math.h>

#define NB 4
#define CC 256
#define HEADS 4
#define DH 64
#define LL 4096
#define GROUPS 32

// Scratch (allocation-free rule: __device__ globals)
__device__ float  g_xn[NB * CC * LL];
__device__ __half g_qh[NB * HEADS * LL * DH];   // [n][h][l][d]
__device__ __half g_kh[NB * HEADS * LL * DH];   // [n][h][l][d]
__device__ __half g_vh[NB * HEADS * DH * LL];   // [n][h][d][l]
__device__ float  g_ao[NB * CC * LL];
__device__ float  g_wt[4 * CC * CC];            // tf32 Wq(*scale),Wk,Wv,Wp

// ---------------------------------------------------------------------------
// helpers
// ---------------------------------------------------------------------------
__device__ __forceinline__ unsigned f2tf(float x) {
    unsigned u;
    asm("cvt.rna.tf32.f32 %0, %1;" : "=r"(u) : "f"(x));
    return u;
}
__device__ __forceinline__ float f2tff(float x) { return __uint_as_float(f2tf(x)); }
__device__ __forceinline__ float ex2f(float x) {
    float r;
    asm("ex2.approx.ftz.f32 %0, %1;" : "=f"(r) : "f"(x));
    return r;
}
__device__ __forceinline__ void mma_tf32(float* c, const unsigned* a,
                                         unsigned b0, unsigned b1) {
    asm volatile(
        "mma.sync.aligned.m16n8k8.row.col.f32.tf32.tf32.f32 "
        "{%0,%1,%2,%3}, {%4,%5,%6,%7}, {%8,%9}, {%0,%1,%2,%3};"
        : "+f"(c[0]), "+f"(c[1]), "+f"(c[2]), "+f"(c[3])
        : "r"(a[0]), "r"(a[1]), "r"(a[2]), "r"(a[3]), "r"(b0), "r"(b1));
}
__device__ __forceinline__ void mma_f16(float* c, const unsigned* a,
                                        unsigned b0, unsigned b1) {
    asm volatile(
        "mma.sync.aligned.m16n8k16.row.col.f32.f16.f16.f32 "
        "{%0,%1,%2,%3}, {%4,%5,%6,%7}, {%8,%9}, {%0,%1,%2,%3};"
        : "+f"(c[0]), "+f"(c[1]), "+f"(c[2]), "+f"(c[3])
        : "r"(a[0]), "r"(a[1]), "r"(a[2]), "r"(a[3]), "r"(b0), "r"(b1));
}
__device__ __forceinline__ void cp16(void* smem_dst, const void* gmem_src) {
    unsigned sa = (unsigned)__cvta_generic_to_shared(smem_dst);
    asm volatile("cp.async.ca.shared.global [%0], [%1], 16;"
                 :: "r"(sa), "l"(gmem_src) : "memory");
}

// ---------------------------------------------------------------------------
// Weight prep: tf32-round; Wq pre-scaled by dh^-0.5 * log2(e).
// ---------------------------------------------------------------------------
__global__ void wcvt_kernel(const float* __restrict__ Wq, const float* __restrict__ Wk,
                            const float* __restrict__ Wv, const float* __restrict__ Wp,
                            float* __restrict__ wt) {
    const float qscale = 0.125f * 1.44269504088896340736f;
    int i4 = (blockIdx.x * 256 + threadIdx.x) * 4;
    {
        float4 w = *reinterpret_cast<const float4*>(&Wq[i4]);
        *reinterpret_cast<float4*>(&wt[i4]) =
            make_float4(f2tff(w.x * qscale), f2tff(w.y * qscale),
                        f2tff(w.z * qscale), f2tff(w.w * qscale));
    }
    const float* src[3] = {Wk, Wv, Wp};
    #pragma unroll
    for (int m = 0; m < 3; m++) {
        float4 w = *reinterpret_cast<const float4*>(&src[m][i4]);
        *reinterpret_cast<float4*>(&wt[(m + 1) * CC * CC + i4]) =
            make_float4(f2tff(w.x), f2tff(w.y), f2tff(w.z), f2tff(w.w));
    }
}

// ---------------------------------------------------------------------------
// GroupNorm: one block per (n, group). Output tf32-rounded.
// ---------------------------------------------------------------------------
__global__ void gn_kernel(const float* __restrict__ x,
                          const float* __restrict__ gamma,
                          const float* __restrict__ beta,
                          float* __restrict__ xn) {
    int n = blockIdx.x >> 5;
    int g = blockIdx.x & 31;
    const float* xp = x  + (size_t)(n * CC + g * 8) * LL;
    float*       op = xn + (size_t)(n * CC + g * 8) * LL;

    float s = 0.f, ss = 0.f;
    for (int i = threadIdx.x; i < 8 * LL; i += 256) {
        float v = xp[i];
        s += v; ss += v * v;
    }
    __shared__ float rs[256], rss[256];
    rs[threadIdx.x] = s; rss[threadIdx.x] = ss;
    __syncthreads();
    for (int o = 128; o > 0; o >>= 1) {
        if (threadIdx.x < o) {
            rs[threadIdx.x]  += rs[threadIdx.x + o];
            rss[threadIdx.x] += rss[threadIdx.x + o];
        }
        __syncthreads();
    }
    const float invN = 1.f / (8.f * LL);
    float mean = rs[0] * invN;
    float var  = rss[0] * invN - mean * mean;
    float inv  = rsqrtf(var + 1e-5f);
    for (int i = threadIdx.x; i < 8 * LL; i += 256) {
        int c = g * 8 + (i >> 12);
        op[i] = f2tff((xp[i] - mean) * inv * gamma[c] + beta[c]);
    }
}

// ---------------------------------------------------------------------------
// Fused QKV projection (tf32 tensor cores). Epilogue emits __half in
// attention-friendly layouts: Q,K -> [n][h][l][d], V -> [n][h][d][l].
// ---------------------------------------------------------------------------
__global__ void __launch_bounds__(128) qkv_tc_kernel(
        const float* __restrict__ xn, const float* __restrict__ wt,
        __half* __restrict__ qh, __half* __restrict__ kh, __half* __restrict__ vh) {
    __shared__ float Xs[32 * 72];
    __shared__ float Ws[3][64 * 40];

    int n  = blockIdx.z;
    int o0 = blockIdx.y << 6;
    int l0 = blockIdx.x << 6;
    const float* xb = xn + (size_t)n * CC * LL;

    int tid = threadIdx.x;
    int lane = tid & 31, w = tid >> 5;
    int g = lane >> 2, t4 = lane & 3;

    float acc[3][8][4];
    #pragma unroll
    for (int m = 0; m < 3; m++)
        #pragma unroll
        for (int nt = 0; nt < 8; nt++)
            #pragma unroll
            for (int c = 0; c < 4; c++) acc[m][nt][c] = 0.f;

    for (int c0 = 0; c0 < CC; c0 += 32) {
        __syncthreads();
        #pragma unroll
        for (int r = 0; r < 4; r++) {
            int idx = r * 512 + tid * 4;
            int cc = idx >> 6, ll = idx & 63;
            float4 xv = *reinterpret_cast<const float4*>(&xb[(size_t)(c0 + cc) * LL + l0 + ll]);
            *reinterpret_cast<float4*>(&Xs[cc * 72 + ll]) = xv;
        }
        #pragma unroll
        for (int m = 0; m < 3; m++) {
            const float* Wm = wt + m * CC * CC;
            #pragma unroll
            for (int p = 0; p < 4; p++) {
                int oo = (tid >> 3) + p * 16;
                int cc4 = (tid & 7) * 4;
                float4 wv = *reinterpret_cast<const float4*>(&Wm[(o0 + oo) * CC + c0 + cc4]);
                *reinterpret_cast<float4*>(&Ws[m][oo * 40 + cc4]) = wv;
            }
        }
        __syncthreads();

        #pragma unroll
        for (int kt = 0; kt < 4; kt++) {
            int kk = kt * 8;
            unsigned a[3][4];
            #pragma unroll
            for (int m = 0; m < 3; m++) {
                a[m][0] = __float_as_uint(Ws[m][(w * 16 + g) * 40 + kk + t4]);
                a[m][1] = __float_as_uint(Ws[m][(w * 16 + g + 8) * 40 + kk + t4]);
                a[m][2] = __float_as_uint(Ws[m][(w * 16 + g) * 40 + kk + t4 + 4]);
                a[m][3] = __float_as_uint(Ws[m][(w * 16 + g + 8) * 40 + kk + t4 + 4]);
            }
            #pragma unroll
            for (int nt = 0; nt < 8; nt++) {
                unsigned b0 = __float_as_uint(Xs[(kk + t4) * 72 + nt * 8 + g]);
                unsigned b1 = __float_as_uint(Xs[(kk + t4 + 4) * 72 + nt * 8 + g]);
                mma_tf32(acc[0][nt], a[0], b0, b1);
                mma_tf32(acc[1][nt], a[1], b0, b1);
                mma_tf32(acc[2][nt], a[2], b0, b1);
            }
        }
    }

    int orow = o0 + w * 16 + g;
    int h = orow >> 6, d0 = orow & 63;
    size_t nhb = (size_t)(n * HEADS + h);
    __half* qd = qh + nhb * LL * DH;
    __half* kd = kh + nhb * LL * DH;
    __half* vd = vh + nhb * DH * LL;

    #pragma unroll
    for (int nt = 0; nt < 8; nt++) {
        int l = l0 + nt * 8 + 2 * t4;
        qd[(size_t)l * DH + d0]           = __float2half_rn(acc[0][nt][0]);
        qd[(size_t)(l + 1) * DH + d0]     = __float2half_rn(acc[0][nt][1]);
        qd[(size_t)l * DH + d0 + 8]       = __float2half_rn(acc[0][nt][2]);
        qd[(size_t)(l + 1) * DH + d0 + 8] = __float2half_rn(acc[0][nt][3]);
        kd[(size_t)l * DH + d0]           = __float2half_rn(acc[1][nt][0]);
        kd[(size_t)(l + 1) * DH + d0]     = __float2half_rn(acc[1][nt][1]);
        kd[(size_t)l * DH + d0 + 8]       = __float2half_rn(acc[1][nt][2]);
        kd[(size_t)(l + 1) * DH + d0 + 8] = __float2half_rn(acc[1][nt][3]);
        *reinterpret_cast<__half2*>(&vd[(size_t)d0 * LL + l]) =
            __floats2half2_rn(acc[2][nt][0], acc[2][nt][1]);
        *reinterpret_cast<__half2*>(&vd[(size_t)(d0 + 8) * LL + l]) =
            __floats2half2_rn(acc[2][nt][2], acc[2][nt][3]);
    }
}

// ---------------------------------------------------------------------------
// Output projection (tf32) + bias, writes d_out. (unchanged)
// ---------------------------------------------------------------------------
__global__ void __launch_bounds__(128) oproj_tc_kernel(
        const float* __restrict__ ao, const float* __restrict__ wt,
        const float* __restrict__ bias, float* __restrict__ out) {
    __shared__ float Xs[32 * 72];
    __shared__ float Ws[64 * 40];

    int n  = blockIdx.z;
    int o0 = blockIdx.y << 6;
    int l0 = blockIdx.x << 6;
    const float* xb = ao + (size_t)n * CC * LL;

    int tid = threadIdx.x;
    int lane = tid & 31, w = tid >> 5;
    int g = lane >> 2, t4 = lane & 3;

    float acc[8][4];
    #pragma unroll
    for (int nt = 0; nt < 8; nt++)
        #pragma unroll
        for (int c = 0; c < 4; c++) acc[nt][c] = 0.f;

    for (int c0 = 0; c0 < CC; c0 += 32) {
        __syncthreads();
        #pragma unroll
        for (int r = 0; r < 4; r++) {
            int idx = r * 512 + tid * 4;
            int cc = idx >> 6, ll = idx & 63;
            float4 xv = *reinterpret_cast<const float4*>(&xb[(size_t)(c0 + cc) * LL + l0 + ll]);
            *reinterpret_cast<float4*>(&Xs[cc * 72 + ll]) = xv;
        }
        #pragma unroll
        for (int p = 0; p < 4; p++) {
            int oo = (tid >> 3) + p * 16;
            int cc4 = (tid & 7) * 4;
            float4 wv = *reinterpret_cast<const float4*>(&wt[(o0 + oo) * CC + c0 + cc4]);
            *reinterpret_cast<float4*>(&Ws[oo * 40 + cc4]) = wv;
        }
        __syncthreads();

        #pragma unroll
        for (int kt = 0; kt < 4; kt++) {
            int kk = kt * 8;
            unsigned a[4];
            a[0] = __float_as_uint(Ws[(w * 16 + g) * 40 + kk + t4]);
            a[1] = __float_as_uint(Ws[(w * 16 + g + 8) * 40 + kk + t4]);
            a[2] = __float_as_uint(Ws[(w * 16 + g) * 40 + kk + t4 + 4]);
            a[3] = __float_as_uint(Ws[(w * 16 + g + 8) * 40 + kk + t4 + 4]);
            #pragma unroll
            for (int nt = 0; nt < 8; nt++) {
                unsigned b0 = __float_as_uint(Xs[(kk + t4) * 72 + nt * 8 + g]);
                unsigned b1 = __float_as_uint(Xs[(kk + t4 + 4) * 72 + nt * 8 + g]);
                mma_tf32(acc[nt], a, b0, b1);
            }
        }
    }

    int orow = o0 + w * 16 + g;
    float bb0 = bias[orow], bb1 = bias[orow + 8];
    float* op = out + (size_t)n * CC * LL;
    #pragma unroll
    for (int nt = 0; nt < 8; nt++) {
        size_t base = (size_t)orow * LL + l0 + nt * 8 + 2 * t4;
        *reinterpret_cast<float2*>(&op[base]) =
            make_float2(acc[nt][0] + bb0, acc[nt][1] + bb0);
        *reinterpret_cast<float2*>(&op[base + 8 * LL]) =
            make_float2(acc[nt][2] + bb1, acc[nt][3] + bb1);
    }
}

// ---------------------------------------------------------------------------
// Flash attention, fp16 mma m16n8k16, double-buffered K/V via cp.async.
// Smem: Ks[2] + Vs[2] + QPs, each 64x72 halves = 46080 B -> 4 blocks/SM
// (reg-bound; __launch_bounds__(128,4) pins 128 regs).
// ---------------------------------------------------------------------------
#define PH 72
#define NT (LL / 64)

__device__ __forceinline__ void issue_kv_f16(const __half* kb, const __half* vb,
                                             __half* Kbuf, __half* Vbuf,
                                             int lk, int tid) {
    #pragma unroll
    for (int r = 0; r < 4; r++) {
        int cix = r * 128 + tid;
        int row = cix >> 3, c8 = (cix & 7) * 8;
        cp16(&Kbuf[row * PH + c8], &kb[(size_t)(lk + row) * DH + c8]);
        cp16(&Vbuf[row * PH + c8], &vb[(size_t)row * LL + lk + c8]);
    }
    asm volatile("cp.async.commit_group;" ::: "memory");
}

__global__ void __launch_bounds__(128, 4) attn_f16_kernel(
        const __half* __restrict__ q, const __half* __restrict__ k,
        const __half* __restrict__ v, float* __restrict__ ao) {
    extern __shared__ __align__(16) char smc[];
    __half* Ksb0 = reinterpret_cast<__half*>(smc);
    __half* Ksb1 = Ksb0 + 64 * PH;
    __half* Vsb0 = Ksb1 + 64 * PH;
    __half* Vsb1 = Vsb0 + 64 * PH;
    __half* QPs  = Vsb1 + 64 * PH;
    float*  Osf  = reinterpret_cast<float*>(smc);  // epilogue staging [d][i] pad 68

    int nh = blockIdx.y;
    int l0 = blockIdx.x << 6;
    const __half* qb = q + (size_t)nh * LL * DH;
    const __half* kb = k + (size_t)nh * LL * DH;
    const __half* vb = v + (size_t)nh * DH * LL;

    int tid  = threadIdx.x;
    int lane = tid & 31, w = tid >> 5;
    int g = lane >> 2, t4 = lane & 3;
    int row0 = w * 16 + g;

    // Prologue: start tile 0 K/V, then Q (separate group), wait both.
    issue_kv_f16(kb, vb, Ksb0, Vsb0, 0, tid);
    #pragma unroll
    for (int r = 0; r < 4; r++) {
        int cix = r * 128 + tid;
        int row = cix >> 3, c8 = (cix & 7) * 8;
        cp16(&QPs[row * PH + c8], &qb[(size_t)(l0 + row) * DH + c8]);
    }
    asm volatile("cp.async.commit_group;" ::: "memory");
    asm volatile("cp.async.wait_group 0;" ::: "memory");
    __syncthreads();

    // Q fragments (A of m16n8k16)
    unsigned qa[4][4];
    #pragma unroll
    for (int kt = 0; kt < 4; kt++) {
        int kk = kt * 16 + 2 * t4;
        qa[kt][0] = *reinterpret_cast<unsigned*>(&QPs[row0 * PH + kk]);
        qa[kt][1] = *reinterpret_cast<unsigned*>(&QPs[(row0 + 8) * PH + kk]);
        qa[kt][2] = *reinterpret_cast<unsigned*>(&QPs[row0 * PH + kk + 8]);
        qa[kt][3] = *reinterpret_cast<unsigned*>(&QPs[(row0 + 8) * PH + kk + 8]);
    }
    __syncthreads();  // QPs now reusable as Ps

    float m0 = -INFINITY, m1 = -INFINITY, ls0 = 0.f, ls1 = 0.f;
    float o[8][4];
    #pragma unroll
    for (int nt = 0; nt < 8; nt++)
        #pragma unroll
        for (int c = 0; c < 4; c++) o[nt][c] = 0.f;

    for (int jt = 0; jt < NT; jt++) {
        const __half* Ks = (jt & 1) ? Ksb1 : Ksb0;
        const __half* Vs = (jt & 1) ? Vsb1 : Vsb0;
        // Stream next tile into the other buffer; its last readers finished
        // at the trailing barrier of iteration jt-1.
        if (jt + 1 < NT) {
            issue_kv_f16(kb, vb, (jt & 1) ? Ksb0 : Ksb1, (jt & 1) ? Vsb0 : Vsb1,
                         (jt + 1) << 6, tid);
            asm volatile("cp.async.wait_group 1;" ::: "memory");
        } else {
            asm volatile("cp.async.wait_group 0;" ::: "memory");
        }
        __syncthreads();  // tile jt visible to all warps

        // ---- S = Q K^T ----
        float s[8][4];
        #pragma unroll
        for (int nt = 0; nt < 8; nt++)
            #pragma unroll
            for (int c = 0; c < 4; c++) s[nt][c] = 0.f;
        #pragma unroll
        for (int kt = 0; kt < 4; kt++) {
            int kk = kt * 16 + 2 * t4;
            #pragma unroll
            for (int nt = 0; nt < 8; nt++) {
                int col = nt * 8 + g;
                unsigned b0 = *reinterpret_cast<const unsigned*>(&Ks[col * PH + kk]);
                unsigned b1 = *reinterpret_cast<const unsigned*>(&Ks[col * PH + kk + 8]);
                mma_f16(s[nt], qa[kt], b0, b1);
            }
        }

        // ---- online softmax (base-2; scale pre-folded into Wq) ----
        float mx0 = -INFINITY, mx1 = -INFINITY;
        #pragma unroll
        for (int nt = 0; nt < 8; nt++) {
            mx0 = fmaxf(mx0, fmaxf(s[nt][0], s[nt][1]));
            mx1 = fmaxf(mx1, fmaxf(s[nt][2], s[nt][3]));
        }
        mx0 = fmaxf(mx0, __shfl_xor_sync(0xffffffffu, mx0, 1));
        mx0 = fmaxf(mx0, __shfl_xor_sync(0xffffffffu, mx0, 2));
        mx1 = fmaxf(mx1, __shfl_xor_sync(0xffffffffu, mx1, 1));
        mx1 = fmaxf(mx1, __shfl_xor_sync(0xffffffffu, mx1, 2));
        float mn0 = fmaxf(m0, mx0), mn1 = fmaxf(m1, mx1);
        float c0 = ex2f(m0 - mn0), c1 = ex2f(m1 - mn1);
        float rs0 = 0.f, rs1 = 0.f;
        __half* Ps = QPs;
        #pragma unroll
        for (int nt = 0; nt < 8; nt++) {
            float p00 = ex2f(s[nt][0] - mn0);
            float p01 = ex2f(s[nt][1] - mn0);
            float p10 = ex2f(s[nt][2] - mn1);
            float p11 = ex2f(s[nt][3] - mn1);
            rs0 += p00 + p01;
            rs1 += p10 + p11;
            int colc = nt * 8 + 2 * t4;
            *reinterpret_cast<__half2*>(&Ps[row0 * PH + colc]) =
                __floats2half2_rn(p00, p01);
            *reinterpret_cast<__half2*>(&Ps[(row0 + 8) * PH + colc]) =
                __floats2half2_rn(p10, p11);
        }
        rs0 += __shfl_xor_sync(0xffffffffu, rs0, 1);
        rs0 += __shfl_xor_sync(0xffffffffu, rs0, 2);
        rs1 += __shfl_xor_sync(0xffffffffu, rs1, 1);
        rs1 += __shfl_xor_sync(0xffffffffu, rs1, 2);
        ls0 = ls0 * c0 + rs0;
        ls1 = ls1 * c1 + rs1;
        m0 = mn0; m1 = mn1;
        #pragma unroll
        for (int nt = 0; nt < 8; nt++) {
            o[nt][0] *= c0; o[nt][1] *= c0;
            o[nt][2] *= c1; o[nt][3] *= c1;
        }
        __syncwarp();  // P rows are warp-local

        // ---- O += P V^T (B[k=j][n=d] = Vs[d][j]) ----
        #pragma unroll
        for (int kt = 0; kt < 4; kt++) {
            int kk = kt * 16 + 2 * t4;
            unsigned a[4];
            a[0] = *reinterpret_cast<const unsigned*>(&Ps[row0 * PH + kk]);
            a[1] = *reinterpret_cast<const unsigned*>(&Ps[(row0 + 8) * PH + kk]);
            a[2] = *reinterpret_cast<const unsigned*>(&Ps[row0 * PH + kk + 8]);
            a[3] = *reinterpret_cast<const unsigned*>(&Ps[(row0 + 8) * PH + kk + 8]);
            #pragma unroll
            for (int nt = 0; nt < 8; nt++) {
                int col = nt * 8 + g;
                unsigned b0 = *reinterpret_cast<const unsigned*>(&Vs[col * PH + kk]);
                unsigned b1 = *reinterpret_cast<const unsigned*>(&Vs[col * PH + kk + 8]);
                mma_f16(o[nt], a, b0, b1);
            }
        }
        __syncthreads();  // readers done: next iteration may overwrite this buffer
    }

    // ---- normalize, stage O^T f32 [d][i] pad 68 (reuses smem), write ----
    float inv0 = 1.f / ls0, inv1 = 1.f / ls1;
    #pragma unroll
    for (int nt = 0; nt < 8; nt++) {
        int d = nt * 8 + 2 * t4;
        Osf[(d    ) * 68 + row0]     = o[nt][0] * inv0;
        Osf[(d + 1) * 68 + row0]     = o[nt][1] * inv0;
        Osf[(d    ) * 68 + row0 + 8] = o[nt][2] * inv1;
        Osf[(d + 1) * 68 + row0 + 8] = o[nt][3] * inv1;
    }
    __syncthreads();
    #pragma unroll
    for (int r = 0; r < 8; r++) {
        int idx = r * 512 + tid * 4;
        int d = idx >> 6, i = idx & 63;
        float4 val = *reinterpret_cast<const float4*>(&Osf[d * 68 + i]);
        *reinterpret_cast<float4*>(&ao[((size_t)(nh * 64 + d)) * LL + l0 + i]) = val;
    }
}

// ---------------------------------------------------------------------------
extern "C" void kernel_launch(void* const* d_in, const int* in_sizes, int n_in,
                              void* d_out, int out_size) {
    const float* x     = (const float*)d_in[0];
    const float* gamma = (const float*)d_in[1];
    const float* beta  = (const float*)d_in[2];
    const float* Wq    = (const float*)d_in[3];
    const float* Wk    = (const float*)d_in[4];
    const float* Wv    = (const float*)d_in[5];
    const float* Wp    = (const float*)d_in[6];
    const float* bp    = (const float*)d_in[7];
    float* out = (float*)d_out;

    static float *xn = nullptr, *ao, *wt;
    static __half *qh, *kh, *vh;
    static size_t attn_smem = (size_t)(5 * 64 * PH) * sizeof(__half);  // 46080 B
    if (!xn) {
        cudaGetSymbolAddress((void**)&xn, g_xn);
        cudaGetSymbolAddress((void**)&qh, g_qh);
        cudaGetSymbolAddress((void**)&kh, g_kh);
        cudaGetSymbolAddress((void**)&vh, g_vh);
        cudaGetSymbolAddress((void**)&ao, g_ao);
        cudaGetSymbolAddress((void**)&wt, g_wt);
        cudaFuncSetAttribute(attn_f16_kernel,
                             cudaFuncAttributeMaxDynamicSharedMemorySize,
                             (int)attn_smem);
    }

    // Weight tf32 prep (+Wq scaling) + GroupNorm (independent)
    wcvt_kernel<<<CC * CC / (256 * 4), 256>>>(Wq, Wk, Wv, Wp, wt);
    gn_kernel<<<NB * GROUPS, 256>>>(x, gamma, beta, xn);

    // Fused QKV projection (tf32 cores, f16 outputs in attention layouts)
    dim3 pgrid(LL / 64, CC / 64, NB);
    qkv_tc_kernel<<<pgrid, 128>>>(xn, wt, qh, kh, vh);

    // Flash attention (fp16 m16n8k16, double-buffered cp.async K/V)
    attn_f16_kernel<<<dim3(LL / 64, NB * HEADS), 128, attn_smem>>>(qh, kh, vh, ao);

    // Output projection (+bias) straight into d_out (tf32 cores)
    oproj_tc_kernel<<<pgrid, 128>>>(ao, wt + 3 * CC * CC, bp, out);
}

// round 11
// speedup vs baseline: 1.1135x; 1.1135x over previous
#include <cuda_runtime.h>
#include <cuda_fp16.h>
#include <math.h>

#define NB 4
#define CC 256
#define HEADS 4
#define DH 64
#define LL 4096
#define GROUPS 32

// Scratch (allocation-free rule: __device__ globals)
__device__ float  g_xn[NB * CC * LL];
__device__ __half g_qh[NB * HEADS * LL * DH];   // [n][h][l][d]
__device__ __half g_kh[NB * HEADS * LL * DH];   // [n][h][l][d]
__device__ __half g_vh[NB * HEADS * DH * LL];   // [n][h][d][l]
__device__ float  g_ao[NB * CC * LL];
__device__ float  g_wt[4 * CC * CC];            // tf32 Wq(*scale),Wk,Wv,Wp

// ---------------------------------------------------------------------------
// helpers
// ---------------------------------------------------------------------------
__device__ __forceinline__ unsigned f2tf(float x) {
    unsigned u;
    asm("cvt.rna.tf32.f32 %0, %1;" : "=r"(u) : "f"(x));
    return u;
}
__device__ __forceinline__ float f2tff(float x) { return __uint_as_float(f2tf(x)); }
__device__ __forceinline__ float ex2f(float x) {
    float r;
    asm("ex2.approx.ftz.f32 %0, %1;" : "=f"(r) : "f"(x));
    return r;
}
__device__ __forceinline__ unsigned h2_as_u32(__half2 h) {
    return *reinterpret_cast<unsigned*>(&h);
}
__device__ __forceinline__ void mma_tf32(float* c, const unsigned* a,
                                         unsigned b0, unsigned b1) {
    asm volatile(
        "mma.sync.aligned.m16n8k8.row.col.f32.tf32.tf32.f32 "
        "{%0,%1,%2,%3}, {%4,%5,%6,%7}, {%8,%9}, {%0,%1,%2,%3};"
        : "+f"(c[0]), "+f"(c[1]), "+f"(c[2]), "+f"(c[3])
        : "r"(a[0]), "r"(a[1]), "r"(a[2]), "r"(a[3]), "r"(b0), "r"(b1));
}
__device__ __forceinline__ void mma_f16(float* c, const unsigned* a,
                                        unsigned b0, unsigned b1) {
    asm volatile(
        "mma.sync.aligned.m16n8k16.row.col.f32.f16.f16.f32 "
        "{%0,%1,%2,%3}, {%4,%5,%6,%7}, {%8,%9}, {%0,%1,%2,%3};"
        : "+f"(c[0]), "+f"(c[1]), "+f"(c[2]), "+f"(c[3])
        : "r"(a[0]), "r"(a[1]), "r"(a[2]), "r"(a[3]), "r"(b0), "r"(b1));
}
__device__ __forceinline__ void ldsm_x4(unsigned& r0, unsigned& r1,
                                        unsigned& r2, unsigned& r3,
                                        unsigned saddr) {
    asm volatile("ldmatrix.sync.aligned.m8n8.x4.shared.b16 {%0,%1,%2,%3}, [%4];"
                 : "=r"(r0), "=r"(r1), "=r"(r2), "=r"(r3) : "r"(saddr));
}
__device__ __forceinline__ void stsm_x4(unsigned saddr, unsigned r0, unsigned r1,
                                        unsigned r2, unsigned r3) {
    asm volatile("stmatrix.sync.aligned.m8n8.x4.shared.b16 [%0], {%1,%2,%3,%4};"
                 :: "r"(saddr), "r"(r0), "r"(r1), "r"(r2), "r"(r3) : "memory");
}
__device__ __forceinline__ void cp16(void* smem_dst, const void* gmem_src) {
    unsigned sa = (unsigned)__cvta_generic_to_shared(smem_dst);
    asm volatile("cp.async.ca.shared.global [%0], [%1], 16;"
                 :: "r"(sa), "l"(gmem_src) : "memory");
}

// ---------------------------------------------------------------------------
// Weight prep: tf32-round; Wq pre-scaled by dh^-0.5 * log2(e).
// ---------------------------------------------------------------------------
__global__ void wcvt_kernel(const float* __restrict__ Wq, const float* __restrict__ Wk,
                            const float* __restrict__ Wv, const float* __restrict__ Wp,
                            float* __restrict__ wt) {
    const float qscale = 0.125f * 1.44269504088896340736f;
    int i4 = (blockIdx.x * 256 + threadIdx.x) * 4;
    {
        float4 w = *reinterpret_cast<const float4*>(&Wq[i4]);
        *reinterpret_cast<float4*>(&wt[i4]) =
            make_float4(f2tff(w.x * qscale), f2tff(w.y * qscale),
                        f2tff(w.z * qscale), f2tff(w.w * qscale));
    }
    const float* src[3] = {Wk, Wv, Wp};
    #pragma unroll
    for (int m = 0; m < 3; m++) {
        float4 w = *reinterpret_cast<const float4*>(&src[m][i4]);
        *reinterpret_cast<float4*>(&wt[(m + 1) * CC * CC + i4]) =
            make_float4(f2tff(w.x), f2tff(w.y), f2tff(w.z), f2tff(w.w));
    }
}

// ---------------------------------------------------------------------------
// GroupNorm: one block per (n, group). Output tf32-rounded.
// ---------------------------------------------------------------------------
__global__ void gn_kernel(const float* __restrict__ x,
                          const float* __restrict__ gamma,
                          const float* __restrict__ beta,
                          float* __restrict__ xn) {
    int n = blockIdx.x >> 5;
    int g = blockIdx.x & 31;
    const float* xp = x  + (size_t)(n * CC + g * 8) * LL;
    float*       op = xn + (size_t)(n * CC + g * 8) * LL;

    float s = 0.f, ss = 0.f;
    for (int i = threadIdx.x; i < 8 * LL; i += 256) {
        float v = xp[i];
        s += v; ss += v * v;
    }
    __shared__ float rs[256], rss[256];
    rs[threadIdx.x] = s; rss[threadIdx.x] = ss;
    __syncthreads();
    for (int o = 128; o > 0; o >>= 1) {
        if (threadIdx.x < o) {
            rs[threadIdx.x]  += rs[threadIdx.x + o];
            rss[threadIdx.x] += rss[threadIdx.x + o];
        }
        __syncthreads();
    }
    const float invN = 1.f / (8.f * LL);
    float mean = rs[0] * invN;
    float var  = rss[0] * invN - mean * mean;
    float inv  = rsqrtf(var + 1e-5f);
    for (int i = threadIdx.x; i < 8 * LL; i += 256) {
        int c = g * 8 + (i >> 12);
        op[i] = f2tff((xp[i] - mean) * inv * gamma[c] + beta[c]);
    }
}

// ---------------------------------------------------------------------------
// Fused QKV projection (tf32 tensor cores). Epilogue emits __half in
// attention-friendly layouts: Q,K -> [n][h][l][d], V -> [n][h][d][l].
// ---------------------------------------------------------------------------
__global__ void __launch_bounds__(128) qkv_tc_kernel(
        const float* __restrict__ xn, const float* __restrict__ wt,
        __half* __restrict__ qh, __half* __restrict__ kh, __half* __restrict__ vh) {
    __shared__ float Xs[32 * 72];
    __shared__ float Ws[3][64 * 40];

    int n  = blockIdx.z;
    int o0 = blockIdx.y << 6;
    int l0 = blockIdx.x << 6;
    const float* xb = xn + (size_t)n * CC * LL;

    int tid = threadIdx.x;
    int lane = tid & 31, w = tid >> 5;
    int g = lane >> 2, t4 = lane & 3;

    float acc[3][8][4];
    #pragma unroll
    for (int m = 0; m < 3; m++)
        #pragma unroll
        for (int nt = 0; nt < 8; nt++)
            #pragma unroll
            for (int c = 0; c < 4; c++) acc[m][nt][c] = 0.f;

    for (int c0 = 0; c0 < CC; c0 += 32) {
        __syncthreads();
        #pragma unroll
        for (int r = 0; r < 4; r++) {
            int idx = r * 512 + tid * 4;
            int cc = idx >> 6, ll = idx & 63;
            float4 xv = *reinterpret_cast<const float4*>(&xb[(size_t)(c0 + cc) * LL + l0 + ll]);
            *reinterpret_cast<float4*>(&Xs[cc * 72 + ll]) = xv;
        }
        #pragma unroll
        for (int m = 0; m < 3; m++) {
            const float* Wm = wt + m * CC * CC;
            #pragma unroll
            for (int p = 0; p < 4; p++) {
                int oo = (tid >> 3) + p * 16;
                int cc4 = (tid & 7) * 4;
                float4 wv = *reinterpret_cast<const float4*>(&Wm[(o0 + oo) * CC + c0 + cc4]);
                *reinterpret_cast<float4*>(&Ws[m][oo * 40 + cc4]) = wv;
            }
        }
        __syncthreads();

        #pragma unroll
        for (int kt = 0; kt < 4; kt++) {
            int kk = kt * 8;
            unsigned a[3][4];
            #pragma unroll
            for (int m = 0; m < 3; m++) {
                a[m][0] = __float_as_uint(Ws[m][(w * 16 + g) * 40 + kk + t4]);
                a[m][1] = __float_as_uint(Ws[m][(w * 16 + g + 8) * 40 + kk + t4]);
                a[m][2] = __float_as_uint(Ws[m][(w * 16 + g) * 40 + kk + t4 + 4]);
                a[m][3] = __float_as_uint(Ws[m][(w * 16 + g + 8) * 40 + kk + t4 + 4]);
            }
            #pragma unroll
            for (int nt = 0; nt < 8; nt++) {
                unsigned b0 = __float_as_uint(Xs[(kk + t4) * 72 + nt * 8 + g]);
                unsigned b1 = __float_as_uint(Xs[(kk + t4 + 4) * 72 + nt * 8 + g]);
                mma_tf32(acc[0][nt], a[0], b0, b1);
                mma_tf32(acc[1][nt], a[1], b0, b1);
                mma_tf32(acc[2][nt], a[2], b0, b1);
            }
        }
    }

    int orow = o0 + w * 16 + g;
    int h = orow >> 6, d0 = orow & 63;
    size_t nhb = (size_t)(n * HEADS + h);
    __half* qd = qh + nhb * LL * DH;
    __half* kd = kh + nhb * LL * DH;
    __half* vd = vh + nhb * DH * LL;

    #pragma unroll
    for (int nt = 0; nt < 8; nt++) {
        int l = l0 + nt * 8 + 2 * t4;
        qd[(size_t)l * DH + d0]           = __float2half_rn(acc[0][nt][0]);
        qd[(size_t)(l + 1) * DH + d0]     = __float2half_rn(acc[0][nt][1]);
        qd[(size_t)l * DH + d0 + 8]       = __float2half_rn(acc[0][nt][2]);
        qd[(size_t)(l + 1) * DH + d0 + 8] = __float2half_rn(acc[0][nt][3]);
        kd[(size_t)l * DH + d0]           = __float2half_rn(acc[1][nt][0]);
        kd[(size_t)(l + 1) * DH + d0]     = __float2half_rn(acc[1][nt][1]);
        kd[(size_t)l * DH + d0 + 8]       = __float2half_rn(acc[1][nt][2]);
        kd[(size_t)(l + 1) * DH + d0 + 8] = __float2half_rn(acc[1][nt][3]);
        *reinterpret_cast<__half2*>(&vd[(size_t)d0 * LL + l]) =
            __floats2half2_rn(acc[2][nt][0], acc[2][nt][1]);
        *reinterpret_cast<__half2*>(&vd[(size_t)(d0 + 8) * LL + l]) =
            __floats2half2_rn(acc[2][nt][2], acc[2][nt][3]);
    }
}

// ---------------------------------------------------------------------------
// Output projection (tf32) + bias, writes d_out. (unchanged)
// ---------------------------------------------------------------------------
__global__ void __launch_bounds__(128) oproj_tc_kernel(
        const float* __restrict__ ao, const float* __restrict__ wt,
        const float* __restrict__ bias, float* __restrict__ out) {
    __shared__ float Xs[32 * 72];
    __shared__ float Ws[64 * 40];

    int n  = blockIdx.z;
    int o0 = blockIdx.y << 6;
    int l0 = blockIdx.x << 6;
    const float* xb = ao + (size_t)n * CC * LL;

    int tid = threadIdx.x;
    int lane = tid & 31, w = tid >> 5;
    int g = lane >> 2, t4 = lane & 3;

    float acc[8][4];
    #pragma unroll
    for (int nt = 0; nt < 8; nt++)
        #pragma unroll
        for (int c = 0; c < 4; c++) acc[nt][c] = 0.f;

    for (int c0 = 0; c0 < CC; c0 += 32) {
        __syncthreads();
        #pragma unroll
        for (int r = 0; r < 4; r++) {
            int idx = r * 512 + tid * 4;
            int cc = idx >> 6, ll = idx & 63;
            float4 xv = *reinterpret_cast<const float4*>(&xb[(size_t)(c0 + cc) * LL + l0 + ll]);
            *reinterpret_cast<float4*>(&Xs[cc * 72 + ll]) = xv;
        }
        #pragma unroll
        for (int p = 0; p < 4; p++) {
            int oo = (tid >> 3) + p * 16;
            int cc4 = (tid & 7) * 4;
            float4 wv = *reinterpret_cast<const float4*>(&wt[(o0 + oo) * CC + c0 + cc4]);
            *reinterpret_cast<float4*>(&Ws[oo * 40 + cc4]) = wv;
        }
        __syncthreads();

        #pragma unroll
        for (int kt = 0; kt < 4; kt++) {
            int kk = kt * 8;
            unsigned a[4];
            a[0] = __float_as_uint(Ws[(w * 16 + g) * 40 + kk + t4]);
            a[1] = __float_as_uint(Ws[(w * 16 + g + 8) * 40 + kk + t4]);
            a[2] = __float_as_uint(Ws[(w * 16 + g) * 40 + kk + t4 + 4]);
            a[3] = __float_as_uint(Ws[(w * 16 + g + 8) * 40 + kk + t4 + 4]);
            #pragma unroll
            for (int nt = 0; nt < 8; nt++) {
                unsigned b0 = __float_as_uint(Xs[(kk + t4) * 72 + nt * 8 + g]);
                unsigned b1 = __float_as_uint(Xs[(kk + t4 + 4) * 72 + nt * 8 + g]);
                mma_tf32(acc[nt], a, b0, b1);
            }
        }
    }

    int orow = o0 + w * 16 + g;
    float bb0 = bias[orow], bb1 = bias[orow + 8];
    float* op = out + (size_t)n * CC * LL;
    #pragma unroll
    for (int nt = 0; nt < 8; nt++) {
        size_t base = (size_t)orow * LL + l0 + nt * 8 + 2 * t4;
        *reinterpret_cast<float2*>(&op[base]) =
            make_float2(acc[nt][0] + bb0, acc[nt][1] + bb0);
        *reinterpret_cast<float2*>(&op[base + 8 * LL]) =
            make_float2(acc[nt][2] + bb1, acc[nt][3] + bb1);
    }
}

// ---------------------------------------------------------------------------
// Flash attention, fp16 mma m16n8k16, single-buffered cp.async (R8 structure),
// with ALL fragment traffic via ldmatrix.x4 / stmatrix.x4:
// per warp per tile 176 LDS/STS -> 36 LDSM + 4 STSM.
// Smem: Ks [j][d], Vs [d][j], QPs (Q [i][d] then P [i][j]), 64 x 72 halves.
// ---------------------------------------------------------------------------
#define PH 72
#define NT (LL / 64)

__global__ void __launch_bounds__(128) attn_f16_kernel(
        const __half* __restrict__ q, const __half* __restrict__ k,
        const __half* __restrict__ v, float* __restrict__ ao) {
    extern __shared__ __align__(16) char smc[];
    __half* Ks  = reinterpret_cast<__half*>(smc);
    __half* Vs  = Ks + 64 * PH;
    __half* QPs = Vs + 64 * PH;
    float*  Osf = reinterpret_cast<float*>(smc);   // epilogue staging [d][i] pad 68

    int nh = blockIdx.y;
    int l0 = blockIdx.x << 6;
    const __half* qb = q + (size_t)nh * LL * DH;
    const __half* kb = k + (size_t)nh * LL * DH;
    const __half* vb = v + (size_t)nh * DH * LL;

    int tid  = threadIdx.x;
    int lane = tid & 31, w = tid >> 5;
    int g = lane >> 2, t4 = lane & 3;
    int row0 = w * 16 + g;
    int quad = lane >> 3, r8 = lane & 7;

    // Shared-space bases + per-lane ldmatrix/stmatrix offsets (bytes).
    unsigned ks_s  = (unsigned)__cvta_generic_to_shared(Ks);
    unsigned vs_s  = (unsigned)__cvta_generic_to_shared(Vs);
    unsigned qps_s = (unsigned)__cvta_generic_to_shared(QPs);
    // B-type (Ks/Vs, [n][k] rows): m0..m3 = (nt0,k),(nt0,k+8),(nt1,k),(nt1,k+8)
    unsigned offB = (unsigned)(((quad >> 1) * 8 + r8) * (PH * 2) + (quad & 1) * 16);
    // A-type (QPs rows [i][k]): m0..m3 = (r,k),(r+8,k),(r,k+8),(r+8,k+8)
    unsigned offA = (unsigned)((w * 16 + (quad & 1) * 8 + r8) * (PH * 2) + (quad >> 1) * 16);

    // ---- Q tile -> QPs[i][d] via cp.async ----
    #pragma unroll
    for (int r = 0; r < 4; r++) {
        int cix = r * 128 + tid;
        int row = cix >> 3, c8 = (cix & 7) * 8;
        cp16(&QPs[row * PH + c8], &qb[(size_t)(l0 + row) * DH + c8]);
    }
    asm volatile("cp.async.commit_group;" ::: "memory");
    asm volatile("cp.async.wait_group 0;" ::: "memory");
    __syncthreads();

    // Q fragments via ldmatrix (A of m16n8k16)
    unsigned qa[4][4];
    #pragma unroll
    for (int kt = 0; kt < 4; kt++)
        ldsm_x4(qa[kt][0], qa[kt][1], qa[kt][2], qa[kt][3], qps_s + kt * 32 + offA);
    __syncthreads();  // QPs now reusable as Ps

    float m0 = -INFINITY, m1 = -INFINITY, ls0 = 0.f, ls1 = 0.f;
    float o[8][4];
    #pragma unroll
    for (int nt = 0; nt < 8; nt++)
        #pragma unroll
        for (int c = 0; c < 4; c++) o[nt][c] = 0.f;

    for (int jt = 0; jt < NT; jt++) {
        int lk = jt << 6;
        // ---- K,V tiles ----
        #pragma unroll
        for (int r = 0; r < 4; r++) {
            int cix = r * 128 + tid;
            int row = cix >> 3, c8 = (cix & 7) * 8;
            cp16(&Ks[row * PH + c8], &kb[(size_t)(lk + row) * DH + c8]);
            cp16(&Vs[row * PH + c8], &vb[(size_t)row * LL + lk + c8]);
        }
        asm volatile("cp.async.commit_group;" ::: "memory");
        asm volatile("cp.async.wait_group 0;" ::: "memory");
        __syncthreads();

        // ---- S = Q K^T (B frags via ldmatrix.x4, 2 nt per op) ----
        float s[8][4];
        #pragma unroll
        for (int nt = 0; nt < 8; nt++)
            #pragma unroll
            for (int c = 0; c < 4; c++) s[nt][c] = 0.f;
        #pragma unroll
        for (int kt = 0; kt < 4; kt++) {
            #pragma unroll
            for (int ntp = 0; ntp < 4; ntp++) {
                unsigned b0, b1, b2, b3;
                ldsm_x4(b0, b1, b2, b3, ks_s + ntp * (16 * PH * 2) + kt * 32 + offB);
                mma_f16(s[2 * ntp],     qa[kt], b0, b1);
                mma_f16(s[2 * ntp + 1], qa[kt], b2, b3);
            }
        }

        // ---- online softmax (base-2; scale pre-folded into Wq) ----
        float mx0 = -INFINITY, mx1 = -INFINITY;
        #pragma unroll
        for (int nt = 0; nt < 8; nt++) {
            mx0 = fmaxf(mx0, fmaxf(s[nt][0], s[nt][1]));
            mx1 = fmaxf(mx1, fmaxf(s[nt][2], s[nt][3]));
        }
        mx0 = fmaxf(mx0, __shfl_xor_sync(0xffffffffu, mx0, 1));
        mx0 = fmaxf(mx0, __shfl_xor_sync(0xffffffffu, mx0, 2));
        mx1 = fmaxf(mx1, __shfl_xor_sync(0xffffffffu, mx1, 1));
        mx1 = fmaxf(mx1, __shfl_xor_sync(0xffffffffu, mx1, 2));
        float mn0 = fmaxf(m0, mx0), mn1 = fmaxf(m1, mx1);
        float c0 = ex2f(m0 - mn0), c1 = ex2f(m1 - mn1);
        float rs0 = 0.f, rs1 = 0.f;
        unsigned pw0[8], pw1[8];
        #pragma unroll
        for (int nt = 0; nt < 8; nt++) {
            float p00 = ex2f(s[nt][0] - mn0);
            float p01 = ex2f(s[nt][1] - mn0);
            float p10 = ex2f(s[nt][2] - mn1);
            float p11 = ex2f(s[nt][3] - mn1);
            rs0 += p00 + p01;
            rs1 += p10 + p11;
            pw0[nt] = h2_as_u32(__floats2half2_rn(p00, p01));
            pw1[nt] = h2_as_u32(__floats2half2_rn(p10, p11));
        }
        // P tile via stmatrix.x4 (2 nt per op): m0..m3 = (r,nt0),(r+8,nt0),(r,nt1),(r+8,nt1)
        #pragma unroll
        for (int ntp = 0; ntp < 4; ntp++)
            stsm_x4(qps_s + ntp * 32 + offA,
                    pw0[2 * ntp], pw1[2 * ntp], pw0[2 * ntp + 1], pw1[2 * ntp + 1]);
        rs0 += __shfl_xor_sync(0xffffffffu, rs0, 1);
        rs0 += __shfl_xor_sync(0xffffffffu, rs0, 2);
        rs1 += __shfl_xor_sync(0xffffffffu, rs1, 1);
        rs1 += __shfl_xor_sync(0xffffffffu, rs1, 2);
        ls0 = ls0 * c0 + rs0;
        ls1 = ls1 * c1 + rs1;
        m0 = mn0; m1 = mn1;
        #pragma unroll
        for (int nt = 0; nt < 8; nt++) {
            o[nt][0] *= c0; o[nt][1] *= c0;
            o[nt][2] *= c1; o[nt][3] *= c1;
        }
        __syncwarp();  // P rows are warp-local (stmatrix visible to own warp)

        // ---- O += P V^T: A frags from Ps, B frags from Vs (ldmatrix.x4) ----
        #pragma unroll
        for (int kt = 0; kt < 4; kt++) {
            unsigned a[4];
            ldsm_x4(a[0], a[1], a[2], a[3], qps_s + kt * 32 + offA);
            #pragma unroll
            for (int ntp = 0; ntp < 4; ntp++) {
                unsigned b0, b1, b2, b3;
                ldsm_x4(b0, b1, b2, b3, vs_s + ntp * (16 * PH * 2) + kt * 32 + offB);
                mma_f16(o[2 * ntp],     a, b0, b1);
                mma_f16(o[2 * ntp + 1], a, b2, b3);
            }
        }
        __syncthreads();  // done with Ks/Vs/Ps before next tile
    }

    // ---- normalize, stage O^T f32 [d][i] pad 68 (reuses smem), write ----
    float inv0 = 1.f / ls0, inv1 = 1.f / ls1;
    #pragma unroll
    for (int nt = 0; nt < 8; nt++) {
        int d = nt * 8 + 2 * t4;
        Osf[(d    ) * 68 + row0]     = o[nt][0] * inv0;
        Osf[(d + 1) * 68 + row0]     = o[nt][1] * inv0;
        Osf[(d    ) * 68 + row0 + 8] = o[nt][2] * inv1;
        Osf[(d + 1) * 68 + row0 + 8] = o[nt][3] * inv1;
    }
    __syncthreads();
    #pragma unroll
    for (int r = 0; r < 8; r++) {
        int idx = r * 512 + tid * 4;
        int d = idx >> 6, i = idx & 63;
        float4 val = *reinterpret_cast<const float4*>(&Osf[d * 68 + i]);
        *reinterpret_cast<float4*>(&ao[((size_t)(nh * 64 + d)) * LL + l0 + i]) = val;
    }
}

// ---------------------------------------------------------------------------
extern "C" void kernel_launch(void* const* d_in, const int* in_sizes, int n_in,
                              void* d_out, int out_size) {
    const float* x     = (const float*)d_in[0];
    const float* gamma = (const float*)d_in[1];
    const float* beta  = (const float*)d_in[2];
    const float* Wq    = (const float*)d_in[3];
    const float* Wk    = (const float*)d_in[4];
    const float* Wv    = (const float*)d_in[5];
    const float* Wp    = (const float*)d_in[6];
    const float* bp    = (const float*)d_in[7];
    float* out = (float*)d_out;

    static float *xn = nullptr, *ao, *wt;
    static __half *qh, *kh, *vh;
    static size_t attn_smem = (size_t)(3 * 64 * PH) * sizeof(__half);  // 27648 B
    if (!xn) {
        cudaGetSymbolAddress((void**)&xn, g_xn);
        cudaGetSymbolAddress((void**)&qh, g_qh);
        cudaGetSymbolAddress((void**)&kh, g_kh);
        cudaGetSymbolAddress((void**)&vh, g_vh);
        cudaGetSymbolAddress((void**)&ao, g_ao);
        cudaGetSymbolAddress((void**)&wt, g_wt);
        cudaFuncSetAttribute(attn_f16_kernel,
                             cudaFuncAttributeMaxDynamicSharedMemorySize,
                             (int)attn_smem);
    }

    // Weight tf32 prep (+Wq scaling) + GroupNorm (independent)
    wcvt_kernel<<<CC * CC / (256 * 4), 256>>>(Wq, Wk, Wv, Wp, wt);
    gn_kernel<<<NB * GROUPS, 256>>>(x, gamma, beta, xn);

    // Fused QKV projection (tf32 cores, f16 outputs in attention layouts)
    dim3 pgrid(LL / 64, CC / 64, NB);
    qkv_tc_kernel<<<pgrid, 128>>>(xn, wt, qh, kh, vh);

    // Flash attention (fp16 m16n8k16, ldmatrix/stmatrix fragment traffic)
    attn_f16_kernel<<<dim3(LL / 64, NB * HEADS), 128, attn_smem>>>(qh, kh, vh, ao);

    // Output projection (+bias) straight into d_out (tf32 cores)
    oproj_tc_kernel<<<pgrid, 128>>>(ao, wt + 3 * CC * CC, bp, out);
}

// round 12
// speedup vs baseline: 1.1763x; 1.0564x over previous
#include <cuda_runtime.h>
#include <cuda_fp16.h>
#include <math.h>

#define NB 4
#define CC 256
#define HEADS 4
#define DH 64
#define LL 4096
#define GROUPS 32

// Scratch (allocation-free rule: __device__ globals)
__device__ float  g_xn[NB * CC * LL];
__device__ __half g_qh[NB * HEADS * LL * DH];   // [n][h][l][d]
__device__ __half g_kh[NB * HEADS * LL * DH];   // [n][h][l][d]
__device__ __half g_vh[NB * HEADS * DH * LL];   // [n][h][d][l]
__device__ float  g_ao[NB * CC * LL];
__device__ float  g_wt[4 * CC * CC];            // tf32 Wq(*scale),Wk,Wv,Wp

// ---------------------------------------------------------------------------
// helpers
// ---------------------------------------------------------------------------
__device__ __forceinline__ unsigned f2tf(float x) {
    unsigned u;
    asm("cvt.rna.tf32.f32 %0, %1;" : "=r"(u) : "f"(x));
    return u;
}
__device__ __forceinline__ float f2tff(float x) { return __uint_as_float(f2tf(x)); }
__device__ __forceinline__ float ex2f(float x) {
    float r;
    asm("ex2.approx.ftz.f32 %0, %1;" : "=f"(r) : "f"(x));
    return r;
}
__device__ __forceinline__ unsigned h2_as_u32(__half2 h) {
    return *reinterpret_cast<unsigned*>(&h);
}
__device__ __forceinline__ void mma_tf32(float* c, const unsigned* a,
                                         unsigned b0, unsigned b1) {
    asm volatile(
        "mma.sync.aligned.m16n8k8.row.col.f32.tf32.tf32.f32 "
        "{%0,%1,%2,%3}, {%4,%5,%6,%7}, {%8,%9}, {%0,%1,%2,%3};"
        : "+f"(c[0]), "+f"(c[1]), "+f"(c[2]), "+f"(c[3])
        : "r"(a[0]), "r"(a[1]), "r"(a[2]), "r"(a[3]), "r"(b0), "r"(b1));
}
__device__ __forceinline__ void mma_f16(float* c, const unsigned* a,
                                        unsigned b0, unsigned b1) {
    asm volatile(
        "mma.sync.aligned.m16n8k16.row.col.f32.f16.f16.f32 "
        "{%0,%1,%2,%3}, {%4,%5,%6,%7}, {%8,%9}, {%0,%1,%2,%3};"
        : "+f"(c[0]), "+f"(c[1]), "+f"(c[2]), "+f"(c[3])
        : "r"(a[0]), "r"(a[1]), "r"(a[2]), "r"(a[3]), "r"(b0), "r"(b1));
}
__device__ __forceinline__ void ldsm_x4(unsigned& r0, unsigned& r1,
                                        unsigned& r2, unsigned& r3,
                                        unsigned saddr) {
    asm volatile("ldmatrix.sync.aligned.m8n8.x4.shared.b16 {%0,%1,%2,%3}, [%4];"
                 : "=r"(r0), "=r"(r1), "=r"(r2), "=r"(r3) : "r"(saddr));
}
__device__ __forceinline__ void cp16(void* smem_dst, const void* gmem_src) {
    unsigned sa = (unsigned)__cvta_generic_to_shared(smem_dst);
    asm volatile("cp.async.ca.shared.global [%0], [%1], 16;"
                 :: "r"(sa), "l"(gmem_src) : "memory");
}

// ---------------------------------------------------------------------------
// Weight prep: tf32-round; Wq pre-scaled by dh^-0.5 * log2(e).
// ---------------------------------------------------------------------------
__global__ void wcvt_kernel(const float* __restrict__ Wq, const float* __restrict__ Wk,
                            const float* __restrict__ Wv, const float* __restrict__ Wp,
                            float* __restrict__ wt) {
    const float qscale = 0.125f * 1.44269504088896340736f;
    int i4 = (blockIdx.x * 256 + threadIdx.x) * 4;
    {
        float4 w = *reinterpret_cast<const float4*>(&Wq[i4]);
        *reinterpret_cast<float4*>(&wt[i4]) =
            make_float4(f2tff(w.x * qscale), f2tff(w.y * qscale),
                        f2tff(w.z * qscale), f2tff(w.w * qscale));
    }
    const float* src[3] = {Wk, Wv, Wp};
    #pragma unroll
    for (int m = 0; m < 3; m++) {
        float4 w = *reinterpret_cast<const float4*>(&src[m][i4]);
        *reinterpret_cast<float4*>(&wt[(m + 1) * CC * CC + i4]) =
            make_float4(f2tff(w.x), f2tff(w.y), f2tff(w.z), f2tff(w.w));
    }
}

// ---------------------------------------------------------------------------
// GroupNorm: one block per (n, group). Output tf32-rounded.
// ---------------------------------------------------------------------------
__global__ void gn_kernel(const float* __restrict__ x,
                          const float* __restrict__ gamma,
                          const float* __restrict__ beta,
                          float* __restrict__ xn) {
    int n = blockIdx.x >> 5;
    int g = blockIdx.x & 31;
    const float* xp = x  + (size_t)(n * CC + g * 8) * LL;
    float*       op = xn + (size_t)(n * CC + g * 8) * LL;

    float s = 0.f, ss = 0.f;
    for (int i = threadIdx.x; i < 8 * LL; i += 256) {
        float v = xp[i];
        s += v; ss += v * v;
    }
    __shared__ float rs[256], rss[256];
    rs[threadIdx.x] = s; rss[threadIdx.x] = ss;
    __syncthreads();
    for (int o = 128; o > 0; o >>= 1) {
        if (threadIdx.x < o) {
            rs[threadIdx.x]  += rs[threadIdx.x + o];
            rss[threadIdx.x] += rss[threadIdx.x + o];
        }
        __syncthreads();
    }
    const float invN = 1.f / (8.f * LL);
    float mean = rs[0] * invN;
    float var  = rss[0] * invN - mean * mean;
    float inv  = rsqrtf(var + 1e-5f);
    for (int i = threadIdx.x; i < 8 * LL; i += 256) {
        int c = g * 8 + (i >> 12);
        op[i] = f2tff((xp[i] - mean) * inv * gamma[c] + beta[c]);
    }
}

// ---------------------------------------------------------------------------
// Fused QKV projection (tf32 tensor cores). Epilogue emits __half in
// attention-friendly layouts: Q,K -> [n][h][l][d], V -> [n][h][d][l].
// ---------------------------------------------------------------------------
__global__ void __launch_bounds__(128) qkv_tc_kernel(
        const float* __restrict__ xn, const float* __restrict__ wt,
        __half* __restrict__ qh, __half* __restrict__ kh, __half* __restrict__ vh) {
    __shared__ float Xs[32 * 72];
    __shared__ float Ws[3][64 * 40];

    int n  = blockIdx.z;
    int o0 = blockIdx.y << 6;
    int l0 = blockIdx.x << 6;
    const float* xb = xn + (size_t)n * CC * LL;

    int tid = threadIdx.x;
    int lane = tid & 31, w = tid >> 5;
    int g = lane >> 2, t4 = lane & 3;

    float acc[3][8][4];
    #pragma unroll
    for (int m = 0; m < 3; m++)
        #pragma unroll
        for (int nt = 0; nt < 8; nt++)
            #pragma unroll
            for (int c = 0; c < 4; c++) acc[m][nt][c] = 0.f;

    for (int c0 = 0; c0 < CC; c0 += 32) {
        __syncthreads();
        #pragma unroll
        for (int r = 0; r < 4; r++) {
            int idx = r * 512 + tid * 4;
            int cc = idx >> 6, ll = idx & 63;
            float4 xv = *reinterpret_cast<const float4*>(&xb[(size_t)(c0 + cc) * LL + l0 + ll]);
            *reinterpret_cast<float4*>(&Xs[cc * 72 + ll]) = xv;
        }
        #pragma unroll
        for (int m = 0; m < 3; m++) {
            const float* Wm = wt + m * CC * CC;
            #pragma unroll
            for (int p = 0; p < 4; p++) {
                int oo = (tid >> 3) + p * 16;
                int cc4 = (tid & 7) * 4;
                float4 wv = *reinterpret_cast<const float4*>(&Wm[(o0 + oo) * CC + c0 + cc4]);
                *reinterpret_cast<float4*>(&Ws[m][oo * 40 + cc4]) = wv;
            }
        }
        __syncthreads();

        #pragma unroll
        for (int kt = 0; kt < 4; kt++) {
            int kk = kt * 8;
            unsigned a[3][4];
            #pragma unroll
            for (int m = 0; m < 3; m++) {
                a[m][0] = __float_as_uint(Ws[m][(w * 16 + g) * 40 + kk + t4]);
                a[m][1] = __float_as_uint(Ws[m][(w * 16 + g + 8) * 40 + kk + t4]);
                a[m][2] = __float_as_uint(Ws[m][(w * 16 + g) * 40 + kk + t4 + 4]);
                a[m][3] = __float_as_uint(Ws[m][(w * 16 + g + 8) * 40 + kk + t4 + 4]);
            }
            #pragma unroll
            for (int nt = 0; nt < 8; nt++) {
                unsigned b0 = __float_as_uint(Xs[(kk + t4) * 72 + nt * 8 + g]);
                unsigned b1 = __float_as_uint(Xs[(kk + t4 + 4) * 72 + nt * 8 + g]);
                mma_tf32(acc[0][nt], a[0], b0, b1);
                mma_tf32(acc[1][nt], a[1], b0, b1);
                mma_tf32(acc[2][nt], a[2], b0, b1);
            }
        }
    }

    int orow = o0 + w * 16 + g;
    int h = orow >> 6, d0 = orow & 63;
    size_t nhb = (size_t)(n * HEADS + h);
    __half* qd = qh + nhb * LL * DH;
    __half* kd = kh + nhb * LL * DH;
    __half* vd = vh + nhb * DH * LL;

    #pragma unroll
    for (int nt = 0; nt < 8; nt++) {
        int l = l0 + nt * 8 + 2 * t4;
        qd[(size_t)l * DH + d0]           = __float2half_rn(acc[0][nt][0]);
        qd[(size_t)(l + 1) * DH + d0]     = __float2half_rn(acc[0][nt][1]);
        qd[(size_t)l * DH + d0 + 8]       = __float2half_rn(acc[0][nt][2]);
        qd[(size_t)(l + 1) * DH + d0 + 8] = __float2half_rn(acc[0][nt][3]);
        kd[(size_t)l * DH + d0]           = __float2half_rn(acc[1][nt][0]);
        kd[(size_t)(l + 1) * DH + d0]     = __float2half_rn(acc[1][nt][1]);
        kd[(size_t)l * DH + d0 + 8]       = __float2half_rn(acc[1][nt][2]);
        kd[(size_t)(l + 1) * DH + d0 + 8] = __float2half_rn(acc[1][nt][3]);
        *reinterpret_cast<__half2*>(&vd[(size_t)d0 * LL + l]) =
            __floats2half2_rn(acc[2][nt][0], acc[2][nt][1]);
        *reinterpret_cast<__half2*>(&vd[(size_t)(d0 + 8) * LL + l]) =
            __floats2half2_rn(acc[2][nt][2], acc[2][nt][3]);
    }
}

// ---------------------------------------------------------------------------
// Output projection (tf32) + bias, writes d_out. (unchanged)
// ---------------------------------------------------------------------------
__global__ void __launch_bounds__(128) oproj_tc_kernel(
        const float* __restrict__ ao, const float* __restrict__ wt,
        const float* __restrict__ bias, float* __restrict__ out) {
    __shared__ float Xs[32 * 72];
    __shared__ float Ws[64 * 40];

    int n  = blockIdx.z;
    int o0 = blockIdx.y << 6;
    int l0 = blockIdx.x << 6;
    const float* xb = ao + (size_t)n * CC * LL;

    int tid = threadIdx.x;
    int lane = tid & 31, w = tid >> 5;
    int g = lane >> 2, t4 = lane & 3;

    float acc[8][4];
    #pragma unroll
    for (int nt = 0; nt < 8; nt++)
        #pragma unroll
        for (int c = 0; c < 4; c++) acc[nt][c] = 0.f;

    for (int c0 = 0; c0 < CC; c0 += 32) {
        __syncthreads();
        #pragma unroll
        for (int r = 0; r < 4; r++) {
            int idx = r * 512 + tid * 4;
            int cc = idx >> 6, ll = idx & 63;
            float4 xv = *reinterpret_cast<const float4*>(&xb[(size_t)(c0 + cc) * LL + l0 + ll]);
            *reinterpret_cast<float4*>(&Xs[cc * 72 + ll]) = xv;
        }
        #pragma unroll
        for (int p = 0; p < 4; p++) {
            int oo = (tid >> 3) + p * 16;
            int cc4 = (tid & 7) * 4;
            float4 wv = *reinterpret_cast<const float4*>(&wt[(o0 + oo) * CC + c0 + cc4]);
            *reinterpret_cast<float4*>(&Ws[oo * 40 + cc4]) = wv;
        }
        __syncthreads();

        #pragma unroll
        for (int kt = 0; kt < 4; kt++) {
            int kk = kt * 8;
            unsigned a[4];
            a[0] = __float_as_uint(Ws[(w * 16 + g) * 40 + kk + t4]);
            a[1] = __float_as_uint(Ws[(w * 16 + g + 8) * 40 + kk + t4]);
            a[2] = __float_as_uint(Ws[(w * 16 + g) * 40 + kk + t4 + 4]);
            a[3] = __float_as_uint(Ws[(w * 16 + g + 8) * 40 + kk + t4 + 4]);
            #pragma unroll
            for (int nt = 0; nt < 8; nt++) {
                unsigned b0 = __float_as_uint(Xs[(kk + t4) * 72 + nt * 8 + g]);
                unsigned b1 = __float_as_uint(Xs[(kk + t4 + 4) * 72 + nt * 8 + g]);
                mma_tf32(acc[nt], a, b0, b1);
            }
        }
    }

    int orow = o0 + w * 16 + g;
    float bb0 = bias[orow], bb1 = bias[orow + 8];
    float* op = out + (size_t)n * CC * LL;
    #pragma unroll
    for (int nt = 0; nt < 8; nt++) {
        size_t base = (size_t)orow * LL + l0 + nt * 8 + 2 * t4;
        *reinterpret_cast<float2*>(&op[base]) =
            make_float2(acc[nt][0] + bb0, acc[nt][1] + bb0);
        *reinterpret_cast<float2*>(&op[base + 8 * LL]) =
            make_float2(acc[nt][2] + bb1, acc[nt][3] + bb1);
    }
}

// ---------------------------------------------------------------------------
// Flash attention, fp16 mma m16n8k16, register-resident P:
// the S-accumulator fragment layout == PV A-operand fragment layout, so the
// exp'd P values are packed to half2 and fed directly to the PV mma.
// No P smem staging at all. K/V frags via ldmatrix.x4.
// ---------------------------------------------------------------------------
#define PH 72
#define NT (LL / 64)

__global__ void __launch_bounds__(128) attn_f16_kernel(
        const __half* __restrict__ q, const __half* __restrict__ k,
        const __half* __restrict__ v, float* __restrict__ ao) {
    extern __shared__ __align__(16) char smc[];
    __half* Ks = reinterpret_cast<__half*>(smc);
    __half* Vs = Ks + 64 * PH;
    __half* Qs = Vs + 64 * PH;
    float*  Osf = reinterpret_cast<float*>(smc);   // epilogue staging [d][i] pad 68

    int nh = blockIdx.y;
    int l0 = blockIdx.x << 6;
    const __half* qb = q + (size_t)nh * LL * DH;
    const __half* kb = k + (size_t)nh * LL * DH;
    const __half* vb = v + (size_t)nh * DH * LL;

    int tid  = threadIdx.x;
    int lane = tid & 31, w = tid >> 5;
    int g = lane >> 2, t4 = lane & 3;
    int row0 = w * 16 + g;
    int quad = lane >> 3, r8 = lane & 7;

    unsigned ks_s = (unsigned)__cvta_generic_to_shared(Ks);
    unsigned vs_s = (unsigned)__cvta_generic_to_shared(Vs);
    unsigned qs_s = (unsigned)__cvta_generic_to_shared(Qs);
    // B-type (Ks/Vs [n][k] rows): m0..m3 = (nt0,k),(nt0,k+8),(nt1,k),(nt1,k+8)
    unsigned offB = (unsigned)(((quad >> 1) * 8 + r8) * (PH * 2) + (quad & 1) * 16);
    // A-type (Qs [i][k] rows): m0..m3 = (r,k),(r+8,k),(r,k+8),(r+8,k+8)
    unsigned offA = (unsigned)((w * 16 + (quad & 1) * 8 + r8) * (PH * 2) + (quad >> 1) * 16);

    // ---- Q tile -> Qs[i][d] via cp.async ----
    #pragma unroll
    for (int r = 0; r < 4; r++) {
        int cix = r * 128 + tid;
        int row = cix >> 3, c8 = (cix & 7) * 8;
        cp16(&Qs[row * PH + c8], &qb[(size_t)(l0 + row) * DH + c8]);
    }
    asm volatile("cp.async.commit_group;" ::: "memory");
    asm volatile("cp.async.wait_group 0;" ::: "memory");
    __syncthreads();

    // Q fragments via ldmatrix (A of m16n8k16)
    unsigned qa[4][4];
    #pragma unroll
    for (int kt = 0; kt < 4; kt++)
        ldsm_x4(qa[kt][0], qa[kt][1], qa[kt][2], qa[kt][3], qs_s + kt * 32 + offA);

    float m0 = -INFINITY, m1 = -INFINITY, ls0 = 0.f, ls1 = 0.f;
    float o[8][4];
    #pragma unroll
    for (int nt = 0; nt < 8; nt++)
        #pragma unroll
        for (int c = 0; c < 4; c++) o[nt][c] = 0.f;

    for (int jt = 0; jt < NT; jt++) {
        int lk = jt << 6;
        // ---- K,V tiles ----
        #pragma unroll
        for (int r = 0; r < 4; r++) {
            int cix = r * 128 + tid;
            int row = cix >> 3, c8 = (cix & 7) * 8;
            cp16(&Ks[row * PH + c8], &kb[(size_t)(lk + row) * DH + c8]);
            cp16(&Vs[row * PH + c8], &vb[(size_t)row * LL + lk + c8]);
        }
        asm volatile("cp.async.commit_group;" ::: "memory");
        asm volatile("cp.async.wait_group 0;" ::: "memory");
        __syncthreads();

        // ---- S = Q K^T (B frags via ldmatrix.x4, 2 nt per op) ----
        float s[8][4];
        #pragma unroll
        for (int nt = 0; nt < 8; nt++)
            #pragma unroll
            for (int c = 0; c < 4; c++) s[nt][c] = 0.f;
        #pragma unroll
        for (int kt = 0; kt < 4; kt++) {
            #pragma unroll
            for (int ntp = 0; ntp < 4; ntp++) {
                unsigned b0, b1, b2, b3;
                ldsm_x4(b0, b1, b2, b3, ks_s + ntp * (16 * PH * 2) + kt * 32 + offB);
                mma_f16(s[2 * ntp],     qa[kt], b0, b1);
                mma_f16(s[2 * ntp + 1], qa[kt], b2, b3);
            }
        }

        // ---- online softmax (base-2; scale pre-folded into Wq) ----
        float mx0 = -INFINITY, mx1 = -INFINITY;
        #pragma unroll
        for (int nt = 0; nt < 8; nt++) {
            mx0 = fmaxf(mx0, fmaxf(s[nt][0], s[nt][1]));
            mx1 = fmaxf(mx1, fmaxf(s[nt][2], s[nt][3]));
        }
        mx0 = fmaxf(mx0, __shfl_xor_sync(0xffffffffu, mx0, 1));
        mx0 = fmaxf(mx0, __shfl_xor_sync(0xffffffffu, mx0, 2));
        mx1 = fmaxf(mx1, __shfl_xor_sync(0xffffffffu, mx1, 1));
        mx1 = fmaxf(mx1, __shfl_xor_sync(0xffffffffu, mx1, 2));
        float mn0 = fmaxf(m0, mx0), mn1 = fmaxf(m1, mx1);
        float c0 = ex2f(m0 - mn0), c1 = ex2f(m1 - mn1);
        float rs0 = 0.f, rs1 = 0.f;
        unsigned pw0[8], pw1[8];
        #pragma unroll
        for (int nt = 0; nt < 8; nt++) {
            float p00 = ex2f(s[nt][0] - mn0);
            float p01 = ex2f(s[nt][1] - mn0);
            float p10 = ex2f(s[nt][2] - mn1);
            float p11 = ex2f(s[nt][3] - mn1);
            rs0 += p00 + p01;
            rs1 += p10 + p11;
            pw0[nt] = h2_as_u32(__floats2half2_rn(p00, p01));
            pw1[nt] = h2_as_u32(__floats2half2_rn(p10, p11));
        }
        rs0 += __shfl_xor_sync(0xffffffffu, rs0, 1);
        rs0 += __shfl_xor_sync(0xffffffffu, rs0, 2);
        rs1 += __shfl_xor_sync(0xffffffffu, rs1, 1);
        rs1 += __shfl_xor_sync(0xffffffffu, rs1, 2);
        ls0 = ls0 * c0 + rs0;
        ls1 = ls1 * c1 + rs1;
        m0 = mn0; m1 = mn1;
        #pragma unroll
        for (int nt = 0; nt < 8; nt++) {
            o[nt][0] *= c0; o[nt][1] *= c0;
            o[nt][2] *= c1; o[nt][3] *= c1;
        }

        // ---- O += P V^T, P fed straight from registers ----
        // A frag for k-chunk kt: a0 = P(row0, kt*16+2t4..) = pw0[2kt],
        // a1 = pw1[2kt], a2 = pw0[2kt+1], a3 = pw1[2kt+1].
        #pragma unroll
        for (int kt = 0; kt < 4; kt++) {
            unsigned a[4] = {pw0[2 * kt], pw1[2 * kt], pw0[2 * kt + 1], pw1[2 * kt + 1]};
            #pragma unroll
            for (int ntp = 0; ntp < 4; ntp++) {
                unsigned b0, b1, b2, b3;
                ldsm_x4(b0, b1, b2, b3, vs_s + ntp * (16 * PH * 2) + kt * 32 + offB);
                mma_f16(o[2 * ntp],     a, b0, b1);
                mma_f16(o[2 * ntp + 1], a, b2, b3);
            }
        }
        __syncthreads();  // done with Ks/Vs before next tile's loads
    }

    // ---- normalize, stage O^T f32 [d][i] pad 68 (reuses smem), write ----
    float inv0 = 1.f / ls0, inv1 = 1.f / ls1;
    #pragma unroll
    for (int nt = 0; nt < 8; nt++) {
        int d = nt * 8 + 2 * t4;
        Osf[(d    ) * 68 + row0]     = o[nt][0] * inv0;
        Osf[(d + 1) * 68 + row0]     = o[nt][1] * inv0;
        Osf[(d    ) * 68 + row0 + 8] = o[nt][2] * inv1;
        Osf[(d + 1) * 68 + row0 + 8] = o[nt][3] * inv1;
    }
    __syncthreads();
    #pragma unroll
    for (int r = 0; r < 8; r++) {
        int idx = r * 512 + tid * 4;
        int d = idx >> 6, i = idx & 63;
        float4 val = *reinterpret_cast<const float4*>(&Osf[d * 68 + i]);
        *reinterpret_cast<float4*>(&ao[((size_t)(nh * 64 + d)) * LL + l0 + i]) = val;
    }
}

// ---------------------------------------------------------------------------
extern "C" void kernel_launch(void* const* d_in, const int* in_sizes, int n_in,
                              void* d_out, int out_size) {
    const float* x     = (const float*)d_in[0];
    const float* gamma = (const float*)d_in[1];
    const float* beta  = (const float*)d_in[2];
    const float* Wq    = (const float*)d_in[3];
    const float* Wk    = (const float*)d_in[4];
    const float* Wv    = (const float*)d_in[5];
    const float* Wp    = (const float*)d_in[6];
    const float* bp    = (const float*)d_in[7];
    float* out = (float*)d_out;

    static float *xn = nullptr, *ao, *wt;
    static __half *qh, *kh, *vh;
    static size_t attn_smem = (size_t)(3 * 64 * PH) * sizeof(__half);  // 27648 B
    if (!xn) {
        cudaGetSymbolAddress((void**)&xn, g_xn);
        cudaGetSymbolAddress((void**)&qh, g_qh);
        cudaGetSymbolAddress((void**)&kh, g_kh);
        cudaGetSymbolAddress((void**)&vh, g_vh);
        cudaGetSymbolAddress((void**)&ao, g_ao);
        cudaGetSymbolAddress((void**)&wt, g_wt);
        cudaFuncSetAttribute(attn_f16_kernel,
                             cudaFuncAttributeMaxDynamicSharedMemorySize,
                             (int)attn_smem);
    }

    // Weight tf32 prep (+Wq scaling) + GroupNorm (independent)
    wcvt_kernel<<<CC * CC / (256 * 4), 256>>>(Wq, Wk, Wv, Wp, wt);
    gn_kernel<<<NB * GROUPS, 256>>>(x, gamma, beta, xn);

    // Fused QKV projection (tf32 cores, f16 outputs in attention layouts)
    dim3 pgrid(LL / 64, CC / 64, NB);
    qkv_tc_kernel<<<pgrid, 128>>>(xn, wt, qh, kh, vh);

    // Flash attention (fp16 m16n8k16, register-resident P)
    attn_f16_kernel<<<dim3(LL / 64, NB * HEADS), 128, attn_smem>>>(qh, kh, vh, ao);

    // Output projection (+bias) straight into d_out (tf32 cores)
    oproj_tc_kernel<<<pgrid, 128>>>(ao, wt + 3 * CC * CC, bp, out);
}

// round 13
// speedup vs baseline: 1.4117x; 1.2001x over previous
#include <cuda_runtime.h>
#include <cuda_fp16.h>
#include <math.h>

#define NB 4
#define CC 256
#define HEADS 4
#define DH 64
#define LL 4096
#define GROUPS 32

// Scratch (allocation-free rule: __device__ globals)
__device__ __half g_xh[NB * CC * LL];           // GN output, [n][c][l] fp16
__device__ __half g_qh[NB * HEADS * LL * DH];   // [n][h][l][d]
__device__ __half g_kh[NB * HEADS * LL * DH];   // [n][h][l][d]
__device__ __half g_vh[NB * HEADS * DH * LL];   // [n][h][d][l]
__device__ __half g_ao[NB * CC * LL];           // attn output, [c][l] fp16
__device__ __half g_wh[4 * CC * CC];            // fp16 Wq(*scale),Wk,Wv,Wp

// ---------------------------------------------------------------------------
// helpers
// ---------------------------------------------------------------------------
__device__ __forceinline__ float ex2f(float x) {
    float r;
    asm("ex2.approx.ftz.f32 %0, %1;" : "=f"(r) : "f"(x));
    return r;
}
__device__ __forceinline__ unsigned h2_as_u32(__half2 h) {
    return *reinterpret_cast<unsigned*>(&h);
}
__device__ __forceinline__ void mma_f16(float* c, const unsigned* a,
                                        unsigned b0, unsigned b1) {
    asm volatile(
        "mma.sync.aligned.m16n8k16.row.col.f32.f16.f16.f32 "
        "{%0,%1,%2,%3}, {%4,%5,%6,%7}, {%8,%9}, {%0,%1,%2,%3};"
        : "+f"(c[0]), "+f"(c[1]), "+f"(c[2]), "+f"(c[3])
        : "r"(a[0]), "r"(a[1]), "r"(a[2]), "r"(a[3]), "r"(b0), "r"(b1));
}
__device__ __forceinline__ void ldsm_x4(unsigned& r0, unsigned& r1,
                                        unsigned& r2, unsigned& r3,
                                        unsigned saddr) {
    asm volatile("ldmatrix.sync.aligned.m8n8.x4.shared.b16 {%0,%1,%2,%3}, [%4];"
                 : "=r"(r0), "=r"(r1), "=r"(r2), "=r"(r3) : "r"(saddr));
}
__device__ __forceinline__ void ldsm_x4_t(unsigned& r0, unsigned& r1,
                                          unsigned& r2, unsigned& r3,
                                          unsigned saddr) {
    asm volatile("ldmatrix.sync.aligned.m8n8.x4.trans.shared.b16 {%0,%1,%2,%3}, [%4];"
                 : "=r"(r0), "=r"(r1), "=r"(r2), "=r"(r3) : "r"(saddr));
}
__device__ __forceinline__ void cp16(void* smem_dst, const void* gmem_src) {
    unsigned sa = (unsigned)__cvta_generic_to_shared(smem_dst);
    asm volatile("cp.async.ca.shared.global [%0], [%1], 16;"
                 :: "r"(sa), "l"(gmem_src) : "memory");
}

// ---------------------------------------------------------------------------
// Weight prep: fp16-round; Wq pre-scaled by dh^-0.5 * log2(e).
// ---------------------------------------------------------------------------
__global__ void wcvt_kernel(const float* __restrict__ Wq, const float* __restrict__ Wk,
                            const float* __restrict__ Wv, const float* __restrict__ Wp,
                            __half* __restrict__ wh) {
    const float qscale = 0.125f * 1.44269504088896340736f;
    int i4 = (blockIdx.x * 256 + threadIdx.x) * 4;
    {
        float4 w = *reinterpret_cast<const float4*>(&Wq[i4]);
        __half2 h01 = __floats2half2_rn(w.x * qscale, w.y * qscale);
        __half2 h23 = __floats2half2_rn(w.z * qscale, w.w * qscale);
        *reinterpret_cast<uint2*>(&wh[i4]) = make_uint2(h2_as_u32(h01), h2_as_u32(h23));
    }
    const float* src[3] = {Wk, Wv, Wp};
    #pragma unroll
    for (int m = 0; m < 3; m++) {
        float4 w = *reinterpret_cast<const float4*>(&src[m][i4]);
        __half2 h01 = __floats2half2_rn(w.x, w.y);
        __half2 h23 = __floats2half2_rn(w.z, w.w);
        *reinterpret_cast<uint2*>(&wh[(m + 1) * CC * CC + i4]) =
            make_uint2(h2_as_u32(h01), h2_as_u32(h23));
    }
}

// ---------------------------------------------------------------------------
// GroupNorm: one block per (n, group), 1024 threads. Output fp16.
// ---------------------------------------------------------------------------
__global__ void __launch_bounds__(1024) gn_kernel(
        const float* __restrict__ x, const float* __restrict__ gamma,
        const float* __restrict__ beta, __half* __restrict__ xh) {
    int n = blockIdx.x >> 5;
    int g = blockIdx.x & 31;
    const float* xp = x    + (size_t)(n * CC + g * 8) * LL;
    __half*      op = xh   + (size_t)(n * CC + g * 8) * LL;

    float s = 0.f, ss = 0.f;
    for (int i4 = threadIdx.x * 4; i4 < 8 * LL; i4 += 4096) {
        float4 v = *reinterpret_cast<const float4*>(&xp[i4]);
        s  += v.x + v.y + v.z + v.w;
        ss += v.x * v.x + v.y * v.y + v.z * v.z + v.w * v.w;
    }
    __shared__ float rs[1024], rss[1024];
    rs[threadIdx.x] = s; rss[threadIdx.x] = ss;
    __syncthreads();
    for (int o = 512; o > 0; o >>= 1) {
        if (threadIdx.x < o) {
            rs[threadIdx.x]  += rs[threadIdx.x + o];
            rss[threadIdx.x] += rss[threadIdx.x + o];
        }
        __syncthreads();
    }
    const float invN = 1.f / (8.f * LL);
    float mean = rs[0] * invN;
    float var  = rss[0] * invN - mean * mean;
    float inv  = rsqrtf(var + 1e-5f);
    for (int i4 = threadIdx.x * 4; i4 < 8 * LL; i4 += 4096) {
        int c = g * 8 + (i4 >> 12);
        float a = inv * gamma[c];
        float b = beta[c] - mean * a;
        float4 v = *reinterpret_cast<const float4*>(&xp[i4]);
        __half2 h01 = __floats2half2_rn(v.x * a + b, v.y * a + b);
        __half2 h23 = __floats2half2_rn(v.z * a + b, v.w * a + b);
        *reinterpret_cast<uint2*>(&op[i4]) = make_uint2(h2_as_u32(h01), h2_as_u32(h23));
    }
}

// ---------------------------------------------------------------------------
// Fused QKV projection, fp16 m16n8k16. Xs [c][l] tile, B-frags via
// ldmatrix.trans; Ws [o][c] tiles, A-frags via ldmatrix. Epilogue emits
// __half in attention layouts: Q,K -> [n][h][l][d], V -> [n][h][d][l].
// ---------------------------------------------------------------------------
#define PX 72   // Xs row pad (halves), 144 B rows
#define PW 40   // Ws row pad (halves), 80 B rows

__global__ void __launch_bounds__(128) qkv_f16_kernel(
        const __half* __restrict__ xh, const __half* __restrict__ wh,
        __half* __restrict__ qh, __half* __restrict__ kh, __half* __restrict__ vh) {
    __shared__ __half Xs[32 * PX];
    __shared__ __half Ws[3][64 * PW];

    int n  = blockIdx.z;
    int o0 = blockIdx.y << 6;
    int l0 = blockIdx.x << 6;
    const __half* xb = xh + (size_t)n * CC * LL;

    int tid = threadIdx.x;
    int lane = tid & 31, w = tid >> 5;
    int g = lane >> 2, t4 = lane & 3;
    int quad = lane >> 3, r8 = lane & 7;

    unsigned xs_s = (unsigned)__cvta_generic_to_shared(Xs);
    unsigned ws_s[3];
    #pragma unroll
    for (int m = 0; m < 3; m++)
        ws_s[m] = (unsigned)__cvta_generic_to_shared(Ws[m]);
    // B (trans) from Xs[k][n] rows
    unsigned offXB = (unsigned)(((quad & 1) * 8 + r8) * (PX * 2) + (quad >> 1) * 16);
    // A from Ws[m][k] rows
    unsigned offWA = (unsigned)((w * 16 + (quad & 1) * 8 + r8) * (PW * 2) + (quad >> 1) * 16);

    float acc[3][8][4];
    #pragma unroll
    for (int m = 0; m < 3; m++)
        #pragma unroll
        for (int nt = 0; nt < 8; nt++)
            #pragma unroll
            for (int c = 0; c < 4; c++) acc[m][nt][c] = 0.f;

    for (int c0 = 0; c0 < CC; c0 += 32) {
        __syncthreads();
        // Xs: 32 rows x 64 halves (16B chunks: 256 total)
        #pragma unroll
        for (int r = 0; r < 2; r++) {
            int cix = r * 128 + tid;
            int row = cix >> 3, ch = (cix & 7) * 8;
            *reinterpret_cast<float4*>(&Xs[row * PX + ch]) =
                *reinterpret_cast<const float4*>(&xb[(size_t)(c0 + row) * LL + l0 + ch]);
        }
        // Ws: per matrix 64 rows x 32 halves (16B chunks: 256 total)
        #pragma unroll
        for (int m = 0; m < 3; m++) {
            const __half* Wm = wh + m * CC * CC;
            #pragma unroll
            for (int r = 0; r < 2; r++) {
                int cix = r * 128 + tid;
                int row = cix >> 2, ch = (cix & 3) * 8;
                *reinterpret_cast<float4*>(&Ws[m][row * PW + ch]) =
                    *reinterpret_cast<const float4*>(&Wm[(size_t)(o0 + row) * CC + c0 + ch]);
            }
        }
        __syncthreads();

        #pragma unroll
        for (int kt = 0; kt < 2; kt++) {
            unsigned a[3][4];
            #pragma unroll
            for (int m = 0; m < 3; m++)
                ldsm_x4(a[m][0], a[m][1], a[m][2], a[m][3], ws_s[m] + kt * 32 + offWA);
            #pragma unroll
            for (int ntp = 0; ntp < 4; ntp++) {
                unsigned b0, b1, b2, b3;
                ldsm_x4_t(b0, b1, b2, b3,
                          xs_s + kt * (16 * PX * 2) + ntp * 32 + offXB);
                #pragma unroll
                for (int m = 0; m < 3; m++) {
                    mma_f16(acc[m][2 * ntp],     a[m], b0, b1);
                    mma_f16(acc[m][2 * ntp + 1], a[m], b2, b3);
                }
            }
        }
    }

    int orow = o0 + w * 16 + g;
    int h = orow >> 6, d0 = orow & 63;
    size_t nhb = (size_t)(n * HEADS + h);
    __half* qd = qh + nhb * LL * DH;
    __half* kd = kh + nhb * LL * DH;
    __half* vd = vh + nhb * DH * LL;

    #pragma unroll
    for (int nt = 0; nt < 8; nt++) {
        int l = l0 + nt * 8 + 2 * t4;
        qd[(size_t)l * DH + d0]           = __float2half_rn(acc[0][nt][0]);
        qd[(size_t)(l + 1) * DH + d0]     = __float2half_rn(acc[0][nt][1]);
        qd[(size_t)l * DH + d0 + 8]       = __float2half_rn(acc[0][nt][2]);
        qd[(size_t)(l + 1) * DH + d0 + 8] = __float2half_rn(acc[0][nt][3]);
        kd[(size_t)l * DH + d0]           = __float2half_rn(acc[1][nt][0]);
        kd[(size_t)(l + 1) * DH + d0]     = __float2half_rn(acc[1][nt][1]);
        kd[(size_t)l * DH + d0 + 8]       = __float2half_rn(acc[1][nt][2]);
        kd[(size_t)(l + 1) * DH + d0 + 8] = __float2half_rn(acc[1][nt][3]);
        *reinterpret_cast<__half2*>(&vd[(size_t)d0 * LL + l]) =
            __floats2half2_rn(acc[2][nt][0], acc[2][nt][1]);
        *reinterpret_cast<__half2*>(&vd[(size_t)(d0 + 8) * LL + l]) =
            __floats2half2_rn(acc[2][nt][2], acc[2][nt][3]);
    }
}

// ---------------------------------------------------------------------------
// Output projection, fp16 m16n8k16, + bias, f32 out (d_out).
// ---------------------------------------------------------------------------
__global__ void __launch_bounds__(128) oproj_f16_kernel(
        const __half* __restrict__ ao, const __half* __restrict__ wh,
        const float* __restrict__ bias, float* __restrict__ out) {
    __shared__ __half Xs[32 * PX];
    __shared__ __half Ws[64 * PW];

    int n  = blockIdx.z;
    int o0 = blockIdx.y << 6;
    int l0 = blockIdx.x << 6;
    const __half* xb = ao + (size_t)n * CC * LL;

    int tid = threadIdx.x;
    int lane = tid & 31, w = tid >> 5;
    int g = lane >> 2, t4 = lane & 3;
    int quad = lane >> 3, r8 = lane & 7;

    unsigned xs_s = (unsigned)__cvta_generic_to_shared(Xs);
    unsigned ws_s = (unsigned)__cvta_generic_to_shared(Ws);
    unsigned offXB = (unsigned)(((quad & 1) * 8 + r8) * (PX * 2) + (quad >> 1) * 16);
    unsigned offWA = (unsigned)((w * 16 + (quad & 1) * 8 + r8) * (PW * 2) + (quad >> 1) * 16);

    float acc[8][4];
    #pragma unroll
    for (int nt = 0; nt < 8; nt++)
        #pragma unroll
        for (int c = 0; c < 4; c++) acc[nt][c] = 0.f;

    for (int c0 = 0; c0 < CC; c0 += 32) {
        __syncthreads();
        #pragma unroll
        for (int r = 0; r < 2; r++) {
            int cix = r * 128 + tid;
            int row = cix >> 3, ch = (cix & 7) * 8;
            *reinterpret_cast<float4*>(&Xs[row * PX + ch]) =
                *reinterpret_cast<const float4*>(&xb[(size_t)(c0 + row) * LL + l0 + ch]);
        }
        #pragma unroll
        for (int r = 0; r < 2; r++) {
            int cix = r * 128 + tid;
            int row = cix >> 2, ch = (cix & 3) * 8;
            *reinterpret_cast<float4*>(&Ws[row * PW + ch]) =
                *reinterpret_cast<const float4*>(&wh[(size_t)(o0 + row) * CC + c0 + ch]);
        }
        __syncthreads();

        #pragma unroll
        for (int kt = 0; kt < 2; kt++) {
            unsigned a[4];
            ldsm_x4(a[0], a[1], a[2], a[3], ws_s + kt * 32 + offWA);
            #pragma unroll
            for (int ntp = 0; ntp < 4; ntp++) {
                unsigned b0, b1, b2, b3;
                ldsm_x4_t(b0, b1, b2, b3,
                          xs_s + kt * (16 * PX * 2) + ntp * 32 + offXB);
                mma_f16(acc[2 * ntp],     a, b0, b1);
                mma_f16(acc[2 * ntp + 1], a, b2, b3);
            }
        }
    }

    int orow = o0 + w * 16 + g;
    float bb0 = bias[orow], bb1 = bias[orow + 8];
    float* op = out + (size_t)n * CC * LL;
    #pragma unroll
    for (int nt = 0; nt < 8; nt++) {
        size_t base = (size_t)orow * LL + l0 + nt * 8 + 2 * t4;
        *reinterpret_cast<float2*>(&op[base]) =
            make_float2(acc[nt][0] + bb0, acc[nt][1] + bb0);
        *reinterpret_cast<float2*>(&op[base + 8 * LL]) =
            make_float2(acc[nt][2] + bb1, acc[nt][3] + bb1);
    }
}

// ---------------------------------------------------------------------------
// Flash attention, fp16 mma m16n8k16, register-resident P. Mainloop identical
// to R12 (211us); epilogue now emits fp16 ao.
// ---------------------------------------------------------------------------
#define PH 72
#define NT (LL / 64)

__global__ void __launch_bounds__(128) attn_f16_kernel(
        const __half* __restrict__ q, const __half* __restrict__ k,
        const __half* __restrict__ v, __half* __restrict__ ao) {
    extern __shared__ __align__(16) char smc[];
    __half* Ks = reinterpret_cast<__half*>(smc);
    __half* Vs = Ks + 64 * PH;
    __half* Qs = Vs + 64 * PH;
    __half* Osh = reinterpret_cast<__half*>(smc);  // epilogue staging [d][i] pad PH

    int nh = blockIdx.y;
    int l0 = blockIdx.x << 6;
    const __half* qb = q + (size_t)nh * LL * DH;
    const __half* kb = k + (size_t)nh * LL * DH;
    const __half* vb = v + (size_t)nh * DH * LL;

    int tid  = threadIdx.x;
    int lane = tid & 31, w = tid >> 5;
    int g = lane >> 2, t4 = lane & 3;
    int row0 = w * 16 + g;
    int quad = lane >> 3, r8 = lane & 7;

    unsigned ks_s = (unsigned)__cvta_generic_to_shared(Ks);
    unsigned vs_s = (unsigned)__cvta_generic_to_shared(Vs);
    unsigned qs_s = (unsigned)__cvta_generic_to_shared(Qs);
    unsigned offB = (unsigned)(((quad >> 1) * 8 + r8) * (PH * 2) + (quad & 1) * 16);
    unsigned offA = (unsigned)((w * 16 + (quad & 1) * 8 + r8) * (PH * 2) + (quad >> 1) * 16);

    // ---- Q tile -> Qs[i][d] via cp.async ----
    #pragma unroll
    for (int r = 0; r < 4; r++) {
        int cix = r * 128 + tid;
        int row = cix >> 3, c8 = (cix & 7) * 8;
        cp16(&Qs[row * PH + c8], &qb[(size_t)(l0 + row) * DH + c8]);
    }
    asm volatile("cp.async.commit_group;" ::: "memory");
    asm volatile("cp.async.wait_group 0;" ::: "memory");
    __syncthreads();

    unsigned qa[4][4];
    #pragma unroll
    for (int kt = 0; kt < 4; kt++)
        ldsm_x4(qa[kt][0], qa[kt][1], qa[kt][2], qa[kt][3], qs_s + kt * 32 + offA);

    float m0 = -INFINITY, m1 = -INFINITY, ls0 = 0.f, ls1 = 0.f;
    float o[8][4];
    #pragma unroll
    for (int nt = 0; nt < 8; nt++)
        #pragma unroll
        for (int c = 0; c < 4; c++) o[nt][c] = 0.f;

    for (int jt = 0; jt < NT; jt++) {
        int lk = jt << 6;
        #pragma unroll
        for (int r = 0; r < 4; r++) {
            int cix = r * 128 + tid;
            int row = cix >> 3, c8 = (cix & 7) * 8;
            cp16(&Ks[row * PH + c8], &kb[(size_t)(lk + row) * DH + c8]);
            cp16(&Vs[row * PH + c8], &vb[(size_t)row * LL + lk + c8]);
        }
        asm volatile("cp.async.commit_group;" ::: "memory");
        asm volatile("cp.async.wait_group 0;" ::: "memory");
        __syncthreads();

        // ---- S = Q K^T ----
        float s[8][4];
        #pragma unroll
        for (int nt = 0; nt < 8; nt++)
            #pragma unroll
            for (int c = 0; c < 4; c++) s[nt][c] = 0.f;
        #pragma unroll
        for (int kt = 0; kt < 4; kt++) {
            #pragma unroll
            for (int ntp = 0; ntp < 4; ntp++) {
                unsigned b0, b1, b2, b3;
                ldsm_x4(b0, b1, b2, b3, ks_s + ntp * (16 * PH * 2) + kt * 32 + offB);
                mma_f16(s[2 * ntp],     qa[kt], b0, b1);
                mma_f16(s[2 * ntp + 1], qa[kt], b2, b3);
            }
        }

        // ---- online softmax (base-2; scale pre-folded into Wq) ----
        float mx0 = -INFINITY, mx1 = -INFINITY;
        #pragma unroll
        for (int nt = 0; nt < 8; nt++) {
            mx0 = fmaxf(mx0, fmaxf(s[nt][0], s[nt][1]));
            mx1 = fmaxf(mx1, fmaxf(s[nt][2], s[nt][3]));
        }
        mx0 = fmaxf(mx0, __shfl_xor_sync(0xffffffffu, mx0, 1));
        mx0 = fmaxf(mx0, __shfl_xor_sync(0xffffffffu, mx0, 2));
        mx1 = fmaxf(mx1, __shfl_xor_sync(0xffffffffu, mx1, 1));
        mx1 = fmaxf(mx1, __shfl_xor_sync(0xffffffffu, mx1, 2));
        float mn0 = fmaxf(m0, mx0), mn1 = fmaxf(m1, mx1);
        float c0 = ex2f(m0 - mn0), c1 = ex2f(m1 - mn1);
        float rs0 = 0.f, rs1 = 0.f;
        unsigned pw0[8], pw1[8];
        #pragma unroll
        for (int nt = 0; nt < 8; nt++) {
            float p00 = ex2f(s[nt][0] - mn0);
            float p01 = ex2f(s[nt][1] - mn0);
            float p10 = ex2f(s[nt][2] - mn1);
            float p11 = ex2f(s[nt][3] - mn1);
            rs0 += p00 + p01;
            rs1 += p10 + p11;
            pw0[nt] = h2_as_u32(__floats2half2_rn(p00, p01));
            pw1[nt] = h2_as_u32(__floats2half2_rn(p10, p11));
        }
        rs0 += __shfl_xor_sync(0xffffffffu, rs0, 1);
        rs0 += __shfl_xor_sync(0xffffffffu, rs0, 2);
        rs1 += __shfl_xor_sync(0xffffffffu, rs1, 1);
        rs1 += __shfl_xor_sync(0xffffffffu, rs1, 2);
        ls0 = ls0 * c0 + rs0;
        ls1 = ls1 * c1 + rs1;
        m0 = mn0; m1 = mn1;
        #pragma unroll
        for (int nt = 0; nt < 8; nt++) {
            o[nt][0] *= c0; o[nt][1] *= c0;
            o[nt][2] *= c1; o[nt][3] *= c1;
        }

        // ---- O += P V^T, P fed straight from registers ----
        #pragma unroll
        for (int kt = 0; kt < 4; kt++) {
            unsigned a[4] = {pw0[2 * kt], pw1[2 * kt], pw0[2 * kt + 1], pw1[2 * kt + 1]};
            #pragma unroll
            for (int ntp = 0; ntp < 4; ntp++) {
                unsigned b0, b1, b2, b3;
                ldsm_x4(b0, b1, b2, b3, vs_s + ntp * (16 * PH * 2) + kt * 32 + offB);
                mma_f16(o[2 * ntp],     a, b0, b1);
                mma_f16(o[2 * ntp + 1], a, b2, b3);
            }
        }
        __syncthreads();  // done with Ks/Vs before next tile's loads
    }

    // ---- normalize, stage O^T fp16 [d][i] pad PH, coalesced half write ----
    float inv0 = 1.f / ls0, inv1 = 1.f / ls1;
    #pragma unroll
    for (int nt = 0; nt < 8; nt++) {
        int d = nt * 8 + 2 * t4;
        Osh[(d    ) * PH + row0]     = __float2half_rn(o[nt][0] * inv0);
        Osh[(d + 1) * PH + row0]     = __float2half_rn(o[nt][1] * inv0);
        Osh[(d    ) * PH + row0 + 8] = __float2half_rn(o[nt][2] * inv1);
        Osh[(d + 1) * PH + row0 + 8] = __float2half_rn(o[nt][3] * inv1);
    }
    __syncthreads();
    #pragma unroll
    for (int r = 0; r < 4; r++) {
        int cix = r * 128 + tid;
        int d = cix >> 3, i8 = (cix & 7) * 8;
        float4 val = *reinterpret_cast<const float4*>(&Osh[d * PH + i8]);
        *reinterpret_cast<float4*>(&ao[((size_t)(nh * 64 + d)) * LL + l0 + i8]) = val;
    }
}

// ---------------------------------------------------------------------------
extern "C" void kernel_launch(void* const* d_in, const int* in_sizes, int n_in,
                              void* d_out, int out_size) {
    const float* x     = (const float*)d_in[0];
    const float* gamma = (const float*)d_in[1];
    const float* beta  = (const float*)d_in[2];
    const float* Wq    = (const float*)d_in[3];
    const float* Wk    = (const float*)d_in[4];
    const float* Wv    = (const float*)d_in[5];
    const float* Wp    = (const float*)d_in[6];
    const float* bp    = (const float*)d_in[7];
    float* out = (float*)d_out;

    static __half *xh = nullptr, *qh, *kh, *vh, *ao, *wh;
    static size_t attn_smem = (size_t)(3 * 64 * PH) * sizeof(__half);  // 27648 B
    if (!xh) {
        cudaGetSymbolAddress((void**)&xh, g_xh);
        cudaGetSymbolAddress((void**)&qh, g_qh);
        cudaGetSymbolAddress((void**)&kh, g_kh);
        cudaGetSymbolAddress((void**)&vh, g_vh);
        cudaGetSymbolAddress((void**)&ao, g_ao);
        cudaGetSymbolAddress((void**)&wh, g_wh);
        cudaFuncSetAttribute(attn_f16_kernel,
                             cudaFuncAttributeMaxDynamicSharedMemorySize,
                             (int)attn_smem);
    }

    // Weight fp16 prep (+Wq scaling) + GroupNorm (independent)
    wcvt_kernel<<<CC * CC / (256 * 4), 256>>>(Wq, Wk, Wv, Wp, wh);
    gn_kernel<<<NB * GROUPS, 1024>>>(x, gamma, beta, xh);

    // Fused QKV projection (fp16 tensor cores)
    dim3 pgrid(LL / 64, CC / 64, NB);
    qkv_f16_kernel<<<pgrid, 128>>>(xh, wh, qh, kh, vh);

    // Flash attention (fp16 m16n8k16, register-resident P)
    attn_f16_kernel<<<dim3(LL / 64, NB * HEADS), 128, attn_smem>>>(qh, kh, vh, ao);

    // Output projection (+bias) straight into d_out (fp16 tensor cores)
    oproj_f16_kernel<<<pgrid, 128>>>(ao, wh + 3 * CC * CC, bp, out);
}